// round 8
// baseline (speedup 1.0000x reference)
#include <cuda_runtime.h>
#include <cuda_bf16.h>
#include <cstdint>

#define NPG   100
#define DEG   16
#define BLK   256
#define NGRAPH 512
#define KP    108          // W1hl k-stride (words)
#define NPAD  112          // W1hl padded rows

// W1 pre-split into tf32 hi/lo (prep kernel -> main kernel)
__device__ uint32_t W1hi_g[NPAD * KP];
__device__ uint32_t W1lo_g[NPAD * KP];

// ---------------- helpers ----------------
__device__ __forceinline__ uint32_t cvt_tf32(float x) {
    uint32_t r;
    asm("cvt.rna.tf32.f32 %0, %1;" : "=r"(r) : "f"(x));
    return r;
}
__device__ __forceinline__ void mma_tf32(float* acc, const uint32_t* a,
                                         uint32_t b0, uint32_t b1) {
    asm volatile("mma.sync.aligned.m16n8k8.row.col.f32.tf32.tf32.f32 "
                 "{%0,%1,%2,%3}, {%4,%5,%6,%7}, {%8,%9}, {%0,%1,%2,%3};"
                 : "+f"(acc[0]), "+f"(acc[1]), "+f"(acc[2]), "+f"(acc[3])
                 : "r"(a[0]), "r"(a[1]), "r"(a[2]), "r"(a[3]),
                   "r"(b0), "r"(b1));
}
__device__ __forceinline__ unsigned long long f32x2_fma(unsigned long long a,
                                                        unsigned long long b,
                                                        unsigned long long c) {
    unsigned long long d;
    asm("fma.rn.f32x2 %0, %1, %2, %3;" : "=l"(d) : "l"(a), "l"(b), "l"(c));
    return d;
}
__device__ __forceinline__ float f32x2_hsum(unsigned long long v) {
    return __uint_as_float((unsigned)(v & 0xffffffffull))
         + __uint_as_float((unsigned)(v >> 32));
}
__device__ __forceinline__ uint32_t pack_bf(float x, float y) {
    __nv_bfloat16 a = __float2bfloat16(x), b = __float2bfloat16(y);
    return (uint32_t)*(uint16_t*)&a | ((uint32_t)*(uint16_t*)&b << 16);
}

// ====================== prep: W1 -> tf32 hi/lo (zero-padded) ======================
__global__ void prep_kernel(const float* __restrict__ W1) {
    int i = blockIdx.x * blockDim.x + threadIdx.x;
    if (i < NPAD * KP) {
        int n = i / KP, k = i % KP;
        float v = (n < 100 && k < 100) ? W1[n * 100 + k] : 0.f;
        uint32_t h = cvt_tf32(v);
        W1hi_g[i] = h;
        W1lo_g[i] = cvt_tf32(v - __uint_as_float(h));
    }
}

// ====================== fused main kernel ======================
// smem byte offsets
#define B_P16 0                 // [100][50] uint32 (packed bf16 pairs) = 20000
#define B_H1  20000             // [100][100] fp32 h1 = 40000
#define B_W2  60000             // [20][102] fp32 W2 -> later sT[100][20]
#define B_B1  68160             // [100] f32
#define B_B2  68560             // [20]
#define B_HG  68640             // [20]
#define B_VEC 68720             // [32]
#define B_SRC 68848             // [1600] bytes
#define K_BYTES 70448

__global__ __launch_bounds__(BLK, 3)
void gnn_fused_kernel(const float* __restrict__ feat,
                      const int*   __restrict__ edge_src,
                      const float* __restrict__ self_feat,
                      const float* __restrict__ x3d,
                      const float* __restrict__ b1,
                      const float* __restrict__ W2, const float* __restrict__ b2,
                      const float* __restrict__ Wv2, const float* __restrict__ Wo2,
                      const float* __restrict__ g2,  const float* __restrict__ be2,
                      const float* __restrict__ Wv3, const float* __restrict__ Wo3,
                      const float* __restrict__ g3,  const float* __restrict__ be3,
                      const float* __restrict__ Wf1, const float* __restrict__ bf1,
                      const float* __restrict__ Wf2, const float* __restrict__ bf2,
                      float* __restrict__ out)
{
    extern __shared__ unsigned char sm[];
    float* sW2 = (float*)(sm + B_W2);
    float* sB1 = (float*)(sm + B_B1);
    float* sB2 = (float*)(sm + B_B2);
    float* shg = (float*)(sm + B_HG);
    float* sVec = (float*)(sm + B_VEC);
    float* sH1 = (float*)(sm + B_H1);
    unsigned char* sSrc = sm + B_SRC;

    const int g    = blockIdx.x;
    const int tid  = threadIdx.x;
    const int lane = tid & 31;
    const int warp = tid >> 5;
    const int qg   = lane >> 2;
    const int tig  = lane & 3;

    // ---- phase 0 (all threads): W2 tile, biases ----
    {
        const float4* gw2 = (const float4*)W2;
        for (int i = tid; i < 500; i += BLK) {
            float4 v = gw2[i];
            int row = (i * 4) / 100, col = (i * 4) % 100;
            float* d = sW2 + row * 102 + col;
            d[0] = v.x; d[1] = v.y; d[2] = v.z; d[3] = v.w;
        }
        if (tid < 100) sB1[tid] = b1[tid];
        if (tid < 20)  sB2[tid] = b2[tid];
        if (tid < 20)  shg[tid] = 0.f;
    }

    // ---- phase A: warps 0-6 compute P = feat @ W1^T (tf32 hi/lo); warp 7 edges ----
    if (warp < 7) {
        const int m0 = warp * 16;
        const int r0l = m0 + qg, r1l = m0 + 8 + qg;
        const int ar0 = (r0l > 99) ? 99 : r0l;
        const int ar1 = (r1l > 99) ? 99 : r1l;
        const float* arow0 = feat + ((size_t)g * 100 + ar0) * 100;
        const float* arow1 = feat + ((size_t)g * 100 + ar1) * 100;
        uint32_t* P16 = (uint32_t*)(sm + B_P16);

        #pragma unroll 1
        for (int jp = 0; jp < 2; jp++) {
            const int nt0 = jp * 7;
            float acc[7][4];
            #pragma unroll
            for (int j = 0; j < 7; j++)
                #pragma unroll
                for (int q = 0; q < 4; q++) acc[j][q] = 0.f;

            #pragma unroll 1
            for (int kt = 0; kt < 13; kt++) {
                const int k0 = kt * 8;
                const int kA = k0 + tig;       // <= 99 always
                const int kB = kA + 4;
                float a0f = __ldg(arow0 + kA);
                float a1f = __ldg(arow1 + kA);
                float a2f = (kB < 100) ? __ldg(arow0 + kB) : 0.f;
                float a3f = (kB < 100) ? __ldg(arow1 + kB) : 0.f;
                uint32_t ah[4], al[4];
                ah[0] = cvt_tf32(a0f); al[0] = cvt_tf32(a0f - __uint_as_float(ah[0]));
                ah[1] = cvt_tf32(a1f); al[1] = cvt_tf32(a1f - __uint_as_float(ah[1]));
                ah[2] = cvt_tf32(a2f); al[2] = cvt_tf32(a2f - __uint_as_float(ah[2]));
                ah[3] = cvt_tf32(a3f); al[3] = cvt_tf32(a3f - __uint_as_float(ah[3]));

                #pragma unroll
                for (int j = 0; j < 7; j++) {
                    const int row = (nt0 + j) * 8 + qg;       // < NPAD=112
                    const int idx = row * KP + k0 + tig;
                    uint32_t bh0 = W1hi_g[idx], bh1 = W1hi_g[idx + 4];
                    uint32_t bl0 = W1lo_g[idx], bl1 = W1lo_g[idx + 4];
                    mma_tf32(acc[j], ah, bh0, bh1);
                    mma_tf32(acc[j], ah, bl0, bl1);
                    mma_tf32(acc[j], al, bh0, bh1);
                }
            }
            // epilogue: pack bf16 pairs into sP16
            #pragma unroll
            for (int j = 0; j < 7; j++) {
                const int col = (nt0 + j) * 8 + 2 * tig;
                if (col < 100) {
                    if (r0l < 100)
                        P16[r0l * 50 + col / 2] = pack_bf(acc[j][0], acc[j][1]);
                    if (r1l < 100)
                        P16[r1l * 50 + col / 2] = pack_bf(acc[j][2], acc[j][3]);
                }
            }
        }
    } else {
        // warp 7: local edge ids (bytes)
        const int4* es = (const int4*)(edge_src + (size_t)g * NPG * DEG);
        const int base = g * NPG;
        for (int i = lane; i < 400; i += 32) {
            int4 e = es[i];
            uint32_t b = (uint32_t)(e.x - base)
                       | ((uint32_t)(e.y - base) << 8)
                       | ((uint32_t)(e.z - base) << 16)
                       | ((uint32_t)(e.w - base) << 24);
            ((uint32_t*)(sm + B_SRC))[i] = b;
        }
    }
    __syncthreads();   // S1: P16 + sSrc ready

    // ---- phase B: h1 = relu(mean_e P[src] + b1); gather from smem P16 ----
    {
        const uint32_t* P16 = (const uint32_t*)(sm + B_P16);
        const bool act = (lane < 25);
        float4 bvec = make_float4(0.f, 0.f, 0.f, 0.f);
        if (act) bvec = *(const float4*)(sB1 + 4 * lane);

        for (int n = warp; n < NPG; n += 8) {
            const uint4 w = *(const uint4*)(sSrc + n * DEG);
            if (act) {
                float4 a0 = make_float4(0.f, 0.f, 0.f, 0.f);
                float4 a1 = a0, a2 = a0, a3 = a0;
                #pragma unroll
                for (int b = 0; b < 4; b++) {
                    int s0 = (w.x >> (8 * b)) & 0xff;
                    int s1 = (w.y >> (8 * b)) & 0xff;
                    int s2 = (w.z >> (8 * b)) & 0xff;
                    int s3 = (w.w >> (8 * b)) & 0xff;
                    uint2 v0 = *(const uint2*)(P16 + s0 * 50 + 2 * lane);
                    uint2 v1 = *(const uint2*)(P16 + s1 * 50 + 2 * lane);
                    uint2 v2 = *(const uint2*)(P16 + s2 * 50 + 2 * lane);
                    uint2 v3 = *(const uint2*)(P16 + s3 * 50 + 2 * lane);
                    a0.x += __uint_as_float(v0.x << 16);
                    a0.y += __uint_as_float(v0.x & 0xffff0000u);
                    a0.z += __uint_as_float(v0.y << 16);
                    a0.w += __uint_as_float(v0.y & 0xffff0000u);
                    a1.x += __uint_as_float(v1.x << 16);
                    a1.y += __uint_as_float(v1.x & 0xffff0000u);
                    a1.z += __uint_as_float(v1.y << 16);
                    a1.w += __uint_as_float(v1.y & 0xffff0000u);
                    a2.x += __uint_as_float(v2.x << 16);
                    a2.y += __uint_as_float(v2.x & 0xffff0000u);
                    a2.z += __uint_as_float(v2.y << 16);
                    a2.w += __uint_as_float(v2.y & 0xffff0000u);
                    a3.x += __uint_as_float(v3.x << 16);
                    a3.y += __uint_as_float(v3.x & 0xffff0000u);
                    a3.z += __uint_as_float(v3.y << 16);
                    a3.w += __uint_as_float(v3.y & 0xffff0000u);
                }
                float4 r;
                r.x = fmaxf((a0.x + a1.x + a2.x + a3.x) * (1.f / DEG) + bvec.x, 0.f);
                r.y = fmaxf((a0.y + a1.y + a2.y + a3.y) * (1.f / DEG) + bvec.y, 0.f);
                r.z = fmaxf((a0.z + a1.z + a2.z + a3.z) * (1.f / DEG) + bvec.z, 0.f);
                r.w = fmaxf((a0.w + a1.w + a2.w + a3.w) * (1.f / DEG) + bvec.w, 0.f);
                *(float4*)(sH1 + n * 100 + 4 * lane) = r;
            }
        }
    }
    __syncthreads();   // S2

    // ---- phase C: sT = h1 @ W2^T  (acc in regs; sT overlays W2 after sync) ----
    {
        const int kk = (lane < 20) ? lane : 19;
        const unsigned long long* pb = (const unsigned long long*)(sW2 + kk * 102);
        unsigned long long acc[13];
        #pragma unroll
        for (int i = 0; i < 13; i++) acc[i] = 0ull;

        #pragma unroll 2
        for (int dp = 0; dp < 50; dp++) {
            unsigned long long bv = pb[dp];
            #pragma unroll
            for (int i = 0; i < 13; i++) {
                int n = warp + 8 * i; n = (n > 99) ? 99 : n;
                acc[i] = f32x2_fma(*(const unsigned long long*)(sH1 + n * 100 + 2 * dp),
                                   bv, acc[i]);
            }
        }
        __syncthreads();   // S3: W2/h1 reads done; sT overwrites W2 region
        if (lane < 20) {
            float* sT = sW2;
            #pragma unroll
            for (int i = 0; i < 13; i++) {
                int n = warp + 8 * i;
                if (n > 99) continue;
                sT[n * 20 + lane] = f32x2_hsum(acc[i]);
            }
        }
    }
    __syncthreads();   // S4

    // ---- phase D: h2 = relu(mean_e sT[src] + b2); hg = sum_n h2 ----
    if (lane < 20) {
        const float* sT = sW2;
        float hgacc = 0.f;
        for (int n = warp; n < NPG; n += 8) {
            const unsigned char* sp = sSrc + n * DEG;
            float a = 0.f;
            #pragma unroll
            for (int e = 0; e < DEG; e++)
                a += sT[sp[e] * 20 + lane];
            hgacc += fmaxf(a * (1.f / DEG) + sB2[lane], 0.f);
        }
        atomicAdd(&shg[lane], hgacc);
    }
    __syncthreads();   // S5

    // ---- tail (warp 0): 2x (V@Wo + LN) + MLP ----
    if (warp == 0) {
        float hgk = (lane < 20) ? shg[lane] * (1.f / NPG) : 0.f;

        {
            const float4* xr = (const float4*)(self_feat + (size_t)g * 200);
            const float4* wr = (const float4*)(Wv2 + lane * 200);
            float acc = 0.f;
            #pragma unroll 5
            for (int p = 0; p < 50; p++) {
                float4 a = wr[p], b = xr[p];
                acc += a.x * b.x + a.y * b.y + a.z * b.z + a.w * b.w;
            }
            sVec[lane] = acc;
        }
        __syncwarp();
        float y = 0.f;
        if (lane < 20) {
            const float* wo = Wo2 + lane * 32;
            float z = 0.f;
            #pragma unroll
            for (int j = 0; j < 32; j++) z += wo[j] * sVec[j];
            y = hgk + z;
        }
        float s = y;
        #pragma unroll
        for (int o = 16; o; o >>= 1) s += __shfl_xor_sync(0xffffffffu, s, o);
        float mu = s * (1.f / 20.f);
        float dd = (lane < 20) ? (y - mu) : 0.f;
        float vv = dd * dd;
        #pragma unroll
        for (int o = 16; o; o >>= 1) vv += __shfl_xor_sync(0xffffffffu, vv, o);
        float hg1 = 0.f;
        if (lane < 20)
            hg1 = dd * rsqrtf(vv * (1.f / 20.f) + 1e-5f) * g2[lane] + be2[lane];

        __syncwarp();
        {
            const float4* xr = (const float4*)(x3d + (size_t)g * 100);
            const float4* wr = (const float4*)(Wv3 + lane * 100);
            float acc = 0.f;
            #pragma unroll 5
            for (int p = 0; p < 25; p++) {
                float4 a = wr[p], b = xr[p];
                acc += a.x * b.x + a.y * b.y + a.z * b.z + a.w * b.w;
            }
            sVec[lane] = acc;
        }
        __syncwarp();
        float y2 = 0.f;
        if (lane < 20) {
            const float* wo = Wo3 + lane * 32;
            float z = 0.f;
            #pragma unroll
            for (int j = 0; j < 32; j++) z += wo[j] * sVec[j];
            y2 = hg1 + z;
        }
        float s2 = y2;
        #pragma unroll
        for (int o = 16; o; o >>= 1) s2 += __shfl_xor_sync(0xffffffffu, s2, o);
        float mu2 = s2 * (1.f / 20.f);
        float d2 = (lane < 20) ? (y2 - mu2) : 0.f;
        float v2s = d2 * d2;
        #pragma unroll
        for (int o = 16; o; o >>= 1) v2s += __shfl_xor_sync(0xffffffffu, v2s, o);
        float hg2 = 0.f;
        if (lane < 20)
            hg2 = d2 * rsqrtf(v2s * (1.f / 20.f) + 1e-5f) * g3[lane] + be3[lane];

        __syncwarp();
        if (lane < 20) sVec[lane] = hg2;
        __syncwarp();

        float f = 0.f;
        if (lane < 10) {
            const float* wf = Wf1 + lane * 20;
            float a = bf1[lane];
            #pragma unroll
            for (int k = 0; k < 20; k++) a += wf[k] * sVec[k];
            f = fmaxf(a, 0.f) * Wf2[lane];
        }
        #pragma unroll
        for (int o = 16; o; o >>= 1) f += __shfl_xor_sync(0xffffffffu, f, o);
        if (lane == 0) out[g] = f + bf2[0];
    }
}

// ============================ launch ============================
extern "C" void kernel_launch(void* const* d_in, const int* in_sizes, int n_in,
                              void* d_out, int out_size) {
    const float* feat      = (const float*)d_in[0];
    const int*   edge_src  = (const int*)  d_in[1];
    // d_in[2] = edge_dst: repeat(arange(N), DEG) by construction — implicit
    const float* self_feat = (const float*)d_in[3];
    const float* x3d       = (const float*)d_in[4];
    const float* W1  = (const float*)d_in[5];
    const float* b1  = (const float*)d_in[6];
    const float* W2  = (const float*)d_in[7];
    const float* b2  = (const float*)d_in[8];
    const float* Wv2 = (const float*)d_in[11];
    const float* Wo2 = (const float*)d_in[12];
    const float* g2  = (const float*)d_in[13];
    const float* be2 = (const float*)d_in[14];
    const float* Wv3 = (const float*)d_in[17];
    const float* Wo3 = (const float*)d_in[18];
    const float* g3  = (const float*)d_in[19];
    const float* be3 = (const float*)d_in[20];
    const float* Wf1 = (const float*)d_in[21];
    const float* bf1 = (const float*)d_in[22];
    const float* Wf2 = (const float*)d_in[23];
    const float* bf2 = (const float*)d_in[24];

    prep_kernel<<<(NPAD * KP + 255) / 256, 256>>>(W1);

    cudaFuncSetAttribute(gnn_fused_kernel,
                         cudaFuncAttributeMaxDynamicSharedMemorySize,
                         K_BYTES);
    gnn_fused_kernel<<<NGRAPH, BLK, K_BYTES>>>(
        feat, edge_src, self_feat, x3d,
        b1, W2, b2,
        Wv2, Wo2, g2, be2,
        Wv3, Wo3, g3, be3,
        Wf1, bf1, Wf2, bf2,
        (float*)d_out);
}

// round 9
// speedup vs baseline: 1.9504x; 1.9504x over previous
#include <cuda_runtime.h>
#include <cstdint>

#define NPG   100
#define DEG   16
#define BLK   256
#define NGRAPH 512
#define W1R   104          // padded W1 rows
#define W1S   108          // W1 word stride (conflict-free, verified in gemm1)
#define MS    104          // M/h1 float stride

// W1 as tf32 (single plane), produced by prep kernel
__device__ uint32_t W1t_g[W1R * W1S];

// ---------------- helpers ----------------
__device__ __forceinline__ uint32_t cvt_tf32(float x) {
    uint32_t r;
    asm("cvt.rna.tf32.f32 %0, %1;" : "=r"(r) : "f"(x));
    return r;
}
__device__ __forceinline__ void mma_tf32(float* acc, const uint32_t* a,
                                         uint32_t b0, uint32_t b1) {
    asm volatile("mma.sync.aligned.m16n8k8.row.col.f32.tf32.tf32.f32 "
                 "{%0,%1,%2,%3}, {%4,%5,%6,%7}, {%8,%9}, {%0,%1,%2,%3};"
                 : "+f"(acc[0]), "+f"(acc[1]), "+f"(acc[2]), "+f"(acc[3])
                 : "r"(a[0]), "r"(a[1]), "r"(a[2]), "r"(a[3]),
                   "r"(b0), "r"(b1));
}
__device__ __forceinline__ unsigned long long f32x2_fma(unsigned long long a,
                                                        unsigned long long b,
                                                        unsigned long long c) {
    unsigned long long d;
    asm("fma.rn.f32x2 %0, %1, %2, %3;" : "=l"(d) : "l"(a), "l"(b), "l"(c));
    return d;
}
__device__ __forceinline__ float f32x2_hsum(unsigned long long v) {
    return __uint_as_float((unsigned)(v & 0xffffffffull))
         + __uint_as_float((unsigned)(v >> 32));
}

// ====================== prep: W1 -> tf32 (zero-padded) ======================
__global__ void prep_kernel(const float* __restrict__ W1) {
    int i = blockIdx.x * blockDim.x + threadIdx.x;
    if (i < W1R * W1S) {
        int n = i / W1S, k = i % W1S;
        float v = (n < 100 && k < 100) ? W1[n * 100 + k] : 0.f;
        W1t_g[i] = cvt_tf32(v);
    }
}

// ====================== fused main kernel ======================
// smem byte offsets
#define B_M    0                 // [100][104] f32  M = mean feat[src] -> h1 in place
#define B_W1   41600             // [104][108] u32 tf32 W1
#define B_W2   86528             // [20][102] f32  W2 -> later sT[100][20]
#define B_B1   94688             // [100] f32
#define B_B2   95088             // [20]
#define B_HG   95168             // [20]
#define B_Z2   95248             // [20]
#define B_Z3   95328             // [20]
#define B_V2S  95408             // [32]
#define B_V3S  95536             // [32]
#define B_SRC  95664             // [1600] bytes
#define K_BYTES 97264

__global__ __launch_bounds__(BLK, 2)
void gnn_fused_kernel(const float* __restrict__ feat,
                      const int*   __restrict__ edge_src,
                      const float* __restrict__ self_feat,
                      const float* __restrict__ x3d,
                      const float* __restrict__ b1,
                      const float* __restrict__ W2, const float* __restrict__ b2,
                      const float* __restrict__ Wv2, const float* __restrict__ Wo2,
                      const float* __restrict__ g2,  const float* __restrict__ be2,
                      const float* __restrict__ Wv3, const float* __restrict__ Wo3,
                      const float* __restrict__ g3,  const float* __restrict__ be3,
                      const float* __restrict__ Wf1, const float* __restrict__ bf1,
                      const float* __restrict__ Wf2, const float* __restrict__ bf2,
                      float* __restrict__ out)
{
    extern __shared__ unsigned char sm[];
    float* sM  = (float*)(sm + B_M);     // becomes h1 in place
    uint32_t* sW1 = (uint32_t*)(sm + B_W1);
    float* sW2 = (float*)(sm + B_W2);
    float* sB1 = (float*)(sm + B_B1);
    float* sB2 = (float*)(sm + B_B2);
    float* shg = (float*)(sm + B_HG);
    unsigned char* sSrc = sm + B_SRC;

    const int g    = blockIdx.x;
    const int tid  = threadIdx.x;
    const int lane = tid & 31;
    const int warp = tid >> 5;
    const int qg   = lane >> 2;
    const int tig  = lane & 3;

    // ---- phase 0: stage W1(tf32), W2, biases, edge bytes ----
    {
        const uint4* gw1 = (const uint4*)W1t_g;
        uint4* sw1 = (uint4*)sW1;
        for (int i = tid; i < W1R * W1S / 4; i += BLK) sw1[i] = gw1[i];

        const float4* gw2 = (const float4*)W2;
        for (int i = tid; i < 500; i += BLK) {
            float4 v = gw2[i];
            int row = (i * 4) / 100, col = (i * 4) % 100;
            float* d = sW2 + row * 102 + col;
            d[0] = v.x; d[1] = v.y; d[2] = v.z; d[3] = v.w;
        }
        if (tid < 100) sB1[tid] = b1[tid];
        if (tid < 20)  sB2[tid] = b2[tid];
        if (tid < 20)  shg[tid] = 0.f;
        const int* es = edge_src + (size_t)g * NPG * DEG;
        const int base = g * NPG;
        for (int i = tid; i < NPG * DEG; i += BLK)
            sSrc[i] = (unsigned char)(es[i] - base);
    }
    __syncthreads();   // S0

    // ---- phase G: M = mean_e feat[src]  (gather from global feat, R7-proven) ----
    {
        const float4* Fg = (const float4*)(feat + (size_t)g * NPG * 100);
        const bool act = (lane < 25);
        for (int n = warp; n < NPG; n += 8) {
            const uint4 w = *(const uint4*)(sSrc + n * DEG);
            if (act) {
                float4 a0 = make_float4(0.f, 0.f, 0.f, 0.f);
                float4 a1 = a0, a2 = a0, a3 = a0;
                #pragma unroll
                for (int b = 0; b < 4; b++) {
                    int s0 = (w.x >> (8 * b)) & 0xff;
                    int s1 = (w.y >> (8 * b)) & 0xff;
                    int s2 = (w.z >> (8 * b)) & 0xff;
                    int s3 = (w.w >> (8 * b)) & 0xff;
                    float4 v0 = __ldg(Fg + s0 * 25 + lane);
                    float4 v1 = __ldg(Fg + s1 * 25 + lane);
                    float4 v2 = __ldg(Fg + s2 * 25 + lane);
                    float4 v3 = __ldg(Fg + s3 * 25 + lane);
                    a0.x += v0.x; a0.y += v0.y; a0.z += v0.z; a0.w += v0.w;
                    a1.x += v1.x; a1.y += v1.y; a1.z += v1.z; a1.w += v1.w;
                    a2.x += v2.x; a2.y += v2.y; a2.z += v2.z; a2.w += v2.w;
                    a3.x += v3.x; a3.y += v3.y; a3.z += v3.z; a3.w += v3.w;
                }
                float4 r;
                r.x = (a0.x + a1.x + a2.x + a3.x) * (1.f / DEG);
                r.y = (a0.y + a1.y + a2.y + a3.y) * (1.f / DEG);
                r.z = (a0.z + a1.z + a2.z + a3.z) * (1.f / DEG);
                r.w = (a0.w + a1.w + a2.w + a3.w) * (1.f / DEG);
                *(float4*)(sM + n * MS + 4 * lane) = r;
            }
        }
    }
    __syncthreads();   // S1

    // ---- phase A: h1 = relu(M @ W1^T + b1), tf32 single-pass; warp 7 does z2/z3 ----
    if (warp < 7) {
        const int m0 = warp * 16;
        const int r0l = m0 + qg, r1l = m0 + 8 + qg;

        // load full A strip to regs (rows >= 100 read junk smem; results discarded)
        uint32_t A0[13], A1[13], A2[13], A3[13];
        #pragma unroll
        for (int kt = 0; kt < 13; kt++) {
            const int k = kt * 8 + tig;
            A0[kt] = cvt_tf32(sM[r0l * MS + k]);
            A2[kt] = cvt_tf32(sM[r0l * MS + k + 4]);
            A1[kt] = cvt_tf32(sM[r1l * MS + k]);
            A3[kt] = cvt_tf32(sM[r1l * MS + k + 4]);
        }
        float* sH1 = sM;   // in-place: this warp reads only its own strip (done above)
        #pragma unroll 1
        for (int nt = 0; nt < 13; nt++) {
            float acc[4] = {0.f, 0.f, 0.f, 0.f};
            #pragma unroll
            for (int kt = 0; kt < 13; kt++) {
                const int idx = (nt * 8 + qg) * W1S + kt * 8 + tig;
                uint32_t b0 = sW1[idx], b1v = sW1[idx + 4];
                uint32_t a[4] = { A0[kt], A1[kt], A2[kt], A3[kt] };
                mma_tf32(acc, a, b0, b1v);
            }
            const int col = nt * 8 + 2 * tig;
            if (col < 100) {
                const float bx = sB1[col], by = sB1[col + 1];
                if (r0l < 100) {
                    sH1[r0l * MS + col]     = fmaxf(acc[0] + bx, 0.f);
                    sH1[r0l * MS + col + 1] = fmaxf(acc[1] + by, 0.f);
                }
                if (r1l < 100) {
                    sH1[r1l * MS + col]     = fmaxf(acc[2] + bx, 0.f);
                    sH1[r1l * MS + col + 1] = fmaxf(acc[3] + by, 0.f);
                }
            }
        }
    } else {
        // warp 7: z2 = Wo2 @ (Wv2 @ self_feat[g]);  z3 = Wo3 @ (Wv3 @ x3d[g])
        float* vs2 = (float*)(sm + B_V2S);
        {
            const float4* xr = (const float4*)(self_feat + (size_t)g * 200);
            const float4* wr = (const float4*)(Wv2 + lane * 200);
            float acc = 0.f;
            #pragma unroll 5
            for (int p = 0; p < 50; p++) {
                float4 a = wr[p], b = xr[p];
                acc += a.x * b.x + a.y * b.y + a.z * b.z + a.w * b.w;
            }
            vs2[lane] = acc;
        }
        __syncwarp();
        if (lane < 20) {
            const float* wo = Wo2 + lane * 32;
            float z = 0.f;
            #pragma unroll
            for (int j = 0; j < 32; j++) z += wo[j] * vs2[j];
            ((float*)(sm + B_Z2))[lane] = z;
        }
        __syncwarp();
        float* vs3 = (float*)(sm + B_V3S);
        {
            const float4* xr = (const float4*)(x3d + (size_t)g * 100);
            const float4* wr = (const float4*)(Wv3 + lane * 100);
            float acc = 0.f;
            #pragma unroll 5
            for (int p = 0; p < 25; p++) {
                float4 a = wr[p], b = xr[p];
                acc += a.x * b.x + a.y * b.y + a.z * b.z + a.w * b.w;
            }
            vs3[lane] = acc;
        }
        __syncwarp();
        if (lane < 20) {
            const float* wo = Wo3 + lane * 32;
            float z = 0.f;
            #pragma unroll
            for (int j = 0; j < 32; j++) z += wo[j] * vs3[j];
            ((float*)(sm + B_Z3))[lane] = z;
        }
    }
    __syncthreads();   // S2

    // ---- phase C: sT = h1 @ W2^T  (R7 verbatim, stride MS) ----
    {
        float* sH1 = sM;
        const int kk = (lane < 20) ? lane : 19;
        const unsigned long long* pb = (const unsigned long long*)(sW2 + kk * 102);
        unsigned long long acc[13];
        #pragma unroll
        for (int i = 0; i < 13; i++) acc[i] = 0ull;

        #pragma unroll 2
        for (int dp = 0; dp < 50; dp++) {
            unsigned long long bv = pb[dp];
            #pragma unroll
            for (int i = 0; i < 13; i++) {
                int n = warp + 8 * i; n = (n > 99) ? 99 : n;
                acc[i] = f32x2_fma(*(const unsigned long long*)(sH1 + n * MS + 2 * dp),
                                   bv, acc[i]);
            }
        }
        __syncthreads();   // S3: W2/h1 reads done; sT overlays W2
        if (lane < 20) {
            float* sT = sW2;
            #pragma unroll
            for (int i = 0; i < 13; i++) {
                int n = warp + 8 * i;
                if (n > 99) continue;
                sT[n * 20 + lane] = f32x2_hsum(acc[i]);
            }
        }
    }
    __syncthreads();   // S4

    // ---- phase D: h2 = relu(mean_e sT[src] + b2); hg = sum_n h2 ----
    if (lane < 20) {
        const float* sT = sW2;
        float hgacc = 0.f;
        for (int n = warp; n < NPG; n += 8) {
            const unsigned char* sp = sSrc + n * DEG;
            float a = 0.f;
            #pragma unroll
            for (int e = 0; e < DEG; e++)
                a += sT[sp[e] * 20 + lane];
            hgacc += fmaxf(a * (1.f / DEG) + sB2[lane], 0.f);
        }
        atomicAdd(&shg[lane], hgacc);
    }
    __syncthreads();   // S5

    // ---- tail (warp 0): hg + z2 -> LN -> + z3 -> LN -> MLP ----
    if (warp == 0) {
        const float* z2 = (const float*)(sm + B_Z2);
        const float* z3 = (const float*)(sm + B_Z3);
        float* sVec = (float*)(sm + B_V2S);

        float y = 0.f;
        if (lane < 20) y = shg[lane] * (1.f / NPG) + z2[lane];
        float s = y;
        #pragma unroll
        for (int o = 16; o; o >>= 1) s += __shfl_xor_sync(0xffffffffu, s, o);
        float mu = s * (1.f / 20.f);
        float dd = (lane < 20) ? (y - mu) : 0.f;
        float vv = dd * dd;
        #pragma unroll
        for (int o = 16; o; o >>= 1) vv += __shfl_xor_sync(0xffffffffu, vv, o);
        float hg1 = 0.f;
        if (lane < 20)
            hg1 = dd * rsqrtf(vv * (1.f / 20.f) + 1e-5f) * g2[lane] + be2[lane];

        float y2 = (lane < 20) ? (hg1 + z3[lane]) : 0.f;
        float s2 = y2;
        #pragma unroll
        for (int o = 16; o; o >>= 1) s2 += __shfl_xor_sync(0xffffffffu, s2, o);
        float mu2 = s2 * (1.f / 20.f);
        float d2 = (lane < 20) ? (y2 - mu2) : 0.f;
        float v2s = d2 * d2;
        #pragma unroll
        for (int o = 16; o; o >>= 1) v2s += __shfl_xor_sync(0xffffffffu, v2s, o);
        float hg2 = 0.f;
        if (lane < 20)
            hg2 = d2 * rsqrtf(v2s * (1.f / 20.f) + 1e-5f) * g3[lane] + be3[lane];

        __syncwarp();
        if (lane < 20) sVec[lane] = hg2;
        __syncwarp();

        float f = 0.f;
        if (lane < 10) {
            const float* wf = Wf1 + lane * 20;
            float a = bf1[lane];
            #pragma unroll
            for (int k = 0; k < 20; k++) a += wf[k] * sVec[k];
            f = fmaxf(a, 0.f) * Wf2[lane];
        }
        #pragma unroll
        for (int o = 16; o; o >>= 1) f += __shfl_xor_sync(0xffffffffu, f, o);
        if (lane == 0) out[g] = f + bf2[0];
    }
}

// ============================ launch ============================
extern "C" void kernel_launch(void* const* d_in, const int* in_sizes, int n_in,
                              void* d_out, int out_size) {
    const float* feat      = (const float*)d_in[0];
    const int*   edge_src  = (const int*)  d_in[1];
    // d_in[2] = edge_dst: repeat(arange(N), DEG) by construction — implicit
    const float* self_feat = (const float*)d_in[3];
    const float* x3d       = (const float*)d_in[4];
    const float* W1  = (const float*)d_in[5];
    const float* b1  = (const float*)d_in[6];
    const float* W2  = (const float*)d_in[7];
    const float* b2  = (const float*)d_in[8];
    const float* Wv2 = (const float*)d_in[11];
    const float* Wo2 = (const float*)d_in[12];
    const float* g2  = (const float*)d_in[13];
    const float* be2 = (const float*)d_in[14];
    const float* Wv3 = (const float*)d_in[17];
    const float* Wo3 = (const float*)d_in[18];
    const float* g3  = (const float*)d_in[19];
    const float* be3 = (const float*)d_in[20];
    const float* Wf1 = (const float*)d_in[21];
    const float* bf1 = (const float*)d_in[22];
    const float* Wf2 = (const float*)d_in[23];
    const float* bf2 = (const float*)d_in[24];

    prep_kernel<<<(W1R * W1S + 255) / 256, 256>>>(W1);

    cudaFuncSetAttribute(gnn_fused_kernel,
                         cudaFuncAttributeMaxDynamicSharedMemorySize,
                         K_BYTES);
    gnn_fused_kernel<<<NGRAPH, BLK, K_BYTES>>>(
        feat, edge_src, self_feat, x3d,
        b1, W2, b2,
        Wv2, Wo2, g2, be2,
        Wv3, Wo3, g3, be3,
        Wf1, bf1, Wf2, bf2,
        (float*)d_out);
}

// round 10
// speedup vs baseline: 1.9676x; 1.0088x over previous
#include <cuda_runtime.h>
#include <cuda_bf16.h>
#include <cstdint>

#define NPG   100
#define DEG   16
#define BLK   256
#define NGRAPH 512
#define W1RN  104          // padded W1 rows (13 n-tiles x 8)
#define W1SW  58           // W1 bf16-pair word stride (conflict-free)
#define MS    100          // M/h1 float stride (400B rows, 8/16B aligned)

// W1 packed bf16 pairs [104][58], produced by prep kernel
__device__ uint32_t W1b_g[W1RN * W1SW];

// ---------------- helpers ----------------
__device__ __forceinline__ void mma_bf16(float* c, const uint32_t* a,
                                         uint32_t b0, uint32_t b1) {
    asm volatile("mma.sync.aligned.m16n8k16.row.col.f32.bf16.bf16.f32 "
                 "{%0,%1,%2,%3}, {%4,%5,%6,%7}, {%8,%9}, {%0,%1,%2,%3};"
                 : "+f"(c[0]), "+f"(c[1]), "+f"(c[2]), "+f"(c[3])
                 : "r"(a[0]), "r"(a[1]), "r"(a[2]), "r"(a[3]),
                   "r"(b0), "r"(b1));
}
__device__ __forceinline__ unsigned long long f32x2_fma(unsigned long long a,
                                                        unsigned long long b,
                                                        unsigned long long c) {
    unsigned long long d;
    asm("fma.rn.f32x2 %0, %1, %2, %3;" : "=l"(d) : "l"(a), "l"(b), "l"(c));
    return d;
}
__device__ __forceinline__ float f32x2_hsum(unsigned long long v) {
    return __uint_as_float((unsigned)(v & 0xffffffffull))
         + __uint_as_float((unsigned)(v >> 32));
}
__device__ __forceinline__ uint32_t pack_bf(float x, float y) {
    __nv_bfloat16 a = __float2bfloat16(x), b = __float2bfloat16(y);
    return (uint32_t)*(uint16_t*)&a | ((uint32_t)*(uint16_t*)&b << 16);
}

// ====================== prep: W1 -> packed bf16 pairs (zero-padded) ======================
__global__ void prep_kernel(const float* __restrict__ W1) {
    int i = blockIdx.x * blockDim.x + threadIdx.x;
    if (i < W1RN * W1SW) {
        int n = i / W1SW, w = i % W1SW;
        int k0 = 2 * w, k1 = 2 * w + 1;
        float v0 = (n < 100 && k0 < 100) ? W1[n * 100 + k0] : 0.f;
        float v1 = (n < 100 && k1 < 100) ? W1[n * 100 + k1] : 0.f;
        W1b_g[i] = pack_bf(v0, v1);
    }
}

// ====================== fused main kernel ======================
// smem byte offsets
#define B_M    0                 // [100][100] f32  M = mean feat[src] -> h1 in place
#define B_W1   40000             // [104][58] u32 packed bf16 W1
#define B_W2   64128             // [20][102] f32  W2 -> later sT[100][20]
#define B_B1   72288             // [100] f32
#define B_B2   72688             // [20]
#define B_HG   72768             // [20]
#define B_Z2   72848             // [20]
#define B_Z3   72928             // [20]
#define B_V2S  73008             // [32]
#define B_V3S  73136             // [32]
#define B_SRC  73264             // [1600] bytes
#define K_BYTES 74864

__global__ __launch_bounds__(BLK, 3)
void gnn_fused_kernel(const float* __restrict__ feat,
                      const int*   __restrict__ edge_src,
                      const float* __restrict__ self_feat,
                      const float* __restrict__ x3d,
                      const float* __restrict__ b1,
                      const float* __restrict__ W2, const float* __restrict__ b2,
                      const float* __restrict__ Wv2, const float* __restrict__ Wo2,
                      const float* __restrict__ g2,  const float* __restrict__ be2,
                      const float* __restrict__ Wv3, const float* __restrict__ Wo3,
                      const float* __restrict__ g3,  const float* __restrict__ be3,
                      const float* __restrict__ Wf1, const float* __restrict__ bf1,
                      const float* __restrict__ Wf2, const float* __restrict__ bf2,
                      float* __restrict__ out)
{
    extern __shared__ unsigned char sm[];
    float* sM  = (float*)(sm + B_M);     // becomes h1 in place
    uint32_t* sW1 = (uint32_t*)(sm + B_W1);
    float* sW2 = (float*)(sm + B_W2);
    float* sB1 = (float*)(sm + B_B1);
    float* sB2 = (float*)(sm + B_B2);
    float* shg = (float*)(sm + B_HG);
    unsigned char* sSrc = sm + B_SRC;

    const int g    = blockIdx.x;
    const int tid  = threadIdx.x;
    const int lane = tid & 31;
    const int warp = tid >> 5;
    const int qg   = lane >> 2;
    const int tig  = lane & 3;

    // ---- phase 0: stage W1(bf16), W2, biases, edge bytes ----
    {
        const uint2* gw1 = (const uint2*)W1b_g;
        uint2* sw1 = (uint2*)sW1;
        for (int i = tid; i < W1RN * W1SW / 2; i += BLK) sw1[i] = gw1[i];

        const float4* gw2 = (const float4*)W2;
        for (int i = tid; i < 500; i += BLK) {
            float4 v = gw2[i];
            int row = (i * 4) / 100, col = (i * 4) % 100;
            float* d = sW2 + row * 102 + col;
            d[0] = v.x; d[1] = v.y; d[2] = v.z; d[3] = v.w;
        }
        if (tid < 100) sB1[tid] = b1[tid];
        if (tid < 20)  sB2[tid] = b2[tid];
        if (tid < 20)  shg[tid] = 0.f;
        const int* es = edge_src + (size_t)g * NPG * DEG;
        const int base = g * NPG;
        for (int i = tid; i < NPG * DEG; i += BLK)
            sSrc[i] = (unsigned char)(es[i] - base);
    }
    __syncthreads();   // S0

    // ---- phase G: M = mean_e feat[src]  (gather from global feat) ----
    {
        const float4* Fg = (const float4*)(feat + (size_t)g * NPG * 100);
        const bool act = (lane < 25);
        for (int n = warp; n < NPG; n += 8) {
            const uint4 w = *(const uint4*)(sSrc + n * DEG);
            if (act) {
                float4 a0 = make_float4(0.f, 0.f, 0.f, 0.f);
                float4 a1 = a0, a2 = a0, a3 = a0;
                #pragma unroll
                for (int b = 0; b < 4; b++) {
                    int s0 = (w.x >> (8 * b)) & 0xff;
                    int s1 = (w.y >> (8 * b)) & 0xff;
                    int s2 = (w.z >> (8 * b)) & 0xff;
                    int s3 = (w.w >> (8 * b)) & 0xff;
                    float4 v0 = __ldg(Fg + s0 * 25 + lane);
                    float4 v1 = __ldg(Fg + s1 * 25 + lane);
                    float4 v2 = __ldg(Fg + s2 * 25 + lane);
                    float4 v3 = __ldg(Fg + s3 * 25 + lane);
                    a0.x += v0.x; a0.y += v0.y; a0.z += v0.z; a0.w += v0.w;
                    a1.x += v1.x; a1.y += v1.y; a1.z += v1.z; a1.w += v1.w;
                    a2.x += v2.x; a2.y += v2.y; a2.z += v2.z; a2.w += v2.w;
                    a3.x += v3.x; a3.y += v3.y; a3.z += v3.z; a3.w += v3.w;
                }
                float4 r;
                r.x = (a0.x + a1.x + a2.x + a3.x) * (1.f / DEG);
                r.y = (a0.y + a1.y + a2.y + a3.y) * (1.f / DEG);
                r.z = (a0.z + a1.z + a2.z + a3.z) * (1.f / DEG);
                r.w = (a0.w + a1.w + a2.w + a3.w) * (1.f / DEG);
                *(float4*)(sM + n * MS + 4 * lane) = r;
            }
        }
    }
    __syncthreads();   // S1

    // ---- phase A: h1 = relu(M @ W1^T + b1), single-pass bf16 MMA; warp 7 z2/z3 ----
    if (warp < 7) {
        const int m0 = warp * 16;
        const int r0l = m0 + qg, r1l = m0 + 8 + qg;

        // A fragments: 7 k16-tiles, packed bf16 pairs from fp32 M rows.
        // Rows >=100 read in-bounds junk; their outputs (c[2],c[3]) are discarded.
        uint32_t a[7][4];
        #pragma unroll
        for (int kt = 0; kt < 7; kt++) {
            const int k  = kt * 16 + 2 * tig;
            const int k8 = k + 8;
            float2 p0 = (k  < 100) ? *(const float2*)(sM + r0l * MS + k)
                                   : make_float2(0.f, 0.f);
            float2 p1 = (k  < 100) ? *(const float2*)(sM + r1l * MS + k)
                                   : make_float2(0.f, 0.f);
            float2 p2 = (k8 < 100) ? *(const float2*)(sM + r0l * MS + k8)
                                   : make_float2(0.f, 0.f);
            float2 p3 = (k8 < 100) ? *(const float2*)(sM + r1l * MS + k8)
                                   : make_float2(0.f, 0.f);
            // k=99 boundary: pair (98,99) fully valid; pair starting 100+ zeroed.
            a[kt][0] = pack_bf(p0.x, p0.y);
            a[kt][1] = pack_bf(p1.x, p1.y);
            a[kt][2] = pack_bf(p2.x, p2.y);
            a[kt][3] = pack_bf(p3.x, p3.y);
        }
        float* sH1 = sM;   // in-place: this warp's strip already in regs
        #pragma unroll 1
        for (int nt = 0; nt < 13; nt++) {
            float acc[4] = {0.f, 0.f, 0.f, 0.f};
            #pragma unroll
            for (int kt = 0; kt < 7; kt++) {
                const int idx = (nt * 8 + qg) * W1SW + kt * 8 + tig;
                mma_bf16(acc, a[kt], sW1[idx], sW1[idx + 4]);
            }
            const int col = nt * 8 + 2 * tig;
            if (col < 100) {
                const float bx = sB1[col], by = sB1[col + 1];
                if (r0l < 100) {
                    sH1[r0l * MS + col]     = fmaxf(acc[0] + bx, 0.f);
                    sH1[r0l * MS + col + 1] = fmaxf(acc[1] + by, 0.f);
                }
                if (r1l < 100) {
                    sH1[r1l * MS + col]     = fmaxf(acc[2] + bx, 0.f);
                    sH1[r1l * MS + col + 1] = fmaxf(acc[3] + by, 0.f);
                }
            }
        }
    } else {
        // warp 7: z2 = Wo2 @ (Wv2 @ self_feat[g]);  z3 = Wo3 @ (Wv3 @ x3d[g])
        float* vs2 = (float*)(sm + B_V2S);
        {
            const float4* xr = (const float4*)(self_feat + (size_t)g * 200);
            const float4* wr = (const float4*)(Wv2 + lane * 200);
            float acc = 0.f;
            #pragma unroll 5
            for (int p = 0; p < 50; p++) {
                float4 av = wr[p], bv = xr[p];
                acc += av.x * bv.x + av.y * bv.y + av.z * bv.z + av.w * bv.w;
            }
            vs2[lane] = acc;
        }
        __syncwarp();
        if (lane < 20) {
            const float* wo = Wo2 + lane * 32;
            float z = 0.f;
            #pragma unroll
            for (int j = 0; j < 32; j++) z += wo[j] * vs2[j];
            ((float*)(sm + B_Z2))[lane] = z;
        }
        __syncwarp();
        float* vs3 = (float*)(sm + B_V3S);
        {
            const float4* xr = (const float4*)(x3d + (size_t)g * 100);
            const float4* wr = (const float4*)(Wv3 + lane * 100);
            float acc = 0.f;
            #pragma unroll 5
            for (int p = 0; p < 25; p++) {
                float4 av = wr[p], bv = xr[p];
                acc += av.x * bv.x + av.y * bv.y + av.z * bv.z + av.w * bv.w;
            }
            vs3[lane] = acc;
        }
        __syncwarp();
        if (lane < 20) {
            const float* wo = Wo3 + lane * 32;
            float z = 0.f;
            #pragma unroll
            for (int j = 0; j < 32; j++) z += wo[j] * vs3[j];
            ((float*)(sm + B_Z3))[lane] = z;
        }
    }
    __syncthreads();   // S2

    // ---- phase C: sT = h1 @ W2^T ----
    {
        float* sH1 = sM;
        const int kk = (lane < 20) ? lane : 19;
        const unsigned long long* pb = (const unsigned long long*)(sW2 + kk * 102);
        unsigned long long acc[13];
        #pragma unroll
        for (int i = 0; i < 13; i++) acc[i] = 0ull;

        #pragma unroll 2
        for (int dp = 0; dp < 50; dp++) {
            unsigned long long bv = pb[dp];
            #pragma unroll
            for (int i = 0; i < 13; i++) {
                int n = warp + 8 * i; n = (n > 99) ? 99 : n;
                acc[i] = f32x2_fma(*(const unsigned long long*)(sH1 + n * MS + 2 * dp),
                                   bv, acc[i]);
            }
        }
        __syncthreads();   // S3: W2/h1 reads done; sT overlays W2
        if (lane < 20) {
            float* sT = sW2;
            #pragma unroll
            for (int i = 0; i < 13; i++) {
                int n = warp + 8 * i;
                if (n > 99) continue;
                sT[n * 20 + lane] = f32x2_hsum(acc[i]);
            }
        }
    }
    __syncthreads();   // S4

    // ---- phase D: h2 = relu(mean_e sT[src] + b2); hg = sum_n h2 ----
    if (lane < 20) {
        const float* sT = sW2;
        float hgacc = 0.f;
        for (int n = warp; n < NPG; n += 8) {
            const unsigned char* sp = sSrc + n * DEG;
            float a = 0.f;
            #pragma unroll
            for (int e = 0; e < DEG; e++)
                a += sT[sp[e] * 20 + lane];
            hgacc += fmaxf(a * (1.f / DEG) + sB2[lane], 0.f);
        }
        atomicAdd(&shg[lane], hgacc);
    }
    __syncthreads();   // S5

    // ---- tail (warp 0): hg + z2 -> LN -> + z3 -> LN -> MLP ----
    if (warp == 0) {
        const float* z2 = (const float*)(sm + B_Z2);
        const float* z3 = (const float*)(sm + B_Z3);
        float* sVec = (float*)(sm + B_V2S);

        float y = 0.f;
        if (lane < 20) y = shg[lane] * (1.f / NPG) + z2[lane];
        float s = y;
        #pragma unroll
        for (int o = 16; o; o >>= 1) s += __shfl_xor_sync(0xffffffffu, s, o);
        float mu = s * (1.f / 20.f);
        float dd = (lane < 20) ? (y - mu) : 0.f;
        float vv = dd * dd;
        #pragma unroll
        for (int o = 16; o; o >>= 1) vv += __shfl_xor_sync(0xffffffffu, vv, o);
        float hg1 = 0.f;
        if (lane < 20)
            hg1 = dd * rsqrtf(vv * (1.f / 20.f) + 1e-5f) * g2[lane] + be2[lane];

        float y2 = (lane < 20) ? (hg1 + z3[lane]) : 0.f;
        float s2 = y2;
        #pragma unroll
        for (int o = 16; o; o >>= 1) s2 += __shfl_xor_sync(0xffffffffu, s2, o);
        float mu2 = s2 * (1.f / 20.f);
        float d2 = (lane < 20) ? (y2 - mu2) : 0.f;
        float v2s = d2 * d2;
        #pragma unroll
        for (int o = 16; o; o >>= 1) v2s += __shfl_xor_sync(0xffffffffu, v2s, o);
        float hg2 = 0.f;
        if (lane < 20)
            hg2 = d2 * rsqrtf(v2s * (1.f / 20.f) + 1e-5f) * g3[lane] + be3[lane];

        __syncwarp();
        if (lane < 20) sVec[lane] = hg2;
        __syncwarp();

        float f = 0.f;
        if (lane < 10) {
            const float* wf = Wf1 + lane * 20;
            float a = bf1[lane];
            #pragma unroll
            for (int k = 0; k < 20; k++) a += wf[k] * sVec[k];
            f = fmaxf(a, 0.f) * Wf2[lane];
        }
        #pragma unroll
        for (int o = 16; o; o >>= 1) f += __shfl_xor_sync(0xffffffffu, f, o);
        if (lane == 0) out[g] = f + bf2[0];
    }
}

// ============================ launch ============================
extern "C" void kernel_launch(void* const* d_in, const int* in_sizes, int n_in,
                              void* d_out, int out_size) {
    const float* feat      = (const float*)d_in[0];
    const int*   edge_src  = (const int*)  d_in[1];
    // d_in[2] = edge_dst: repeat(arange(N), DEG) by construction — implicit
    const float* self_feat = (const float*)d_in[3];
    const float* x3d       = (const float*)d_in[4];
    const float* W1  = (const float*)d_in[5];
    const float* b1  = (const float*)d_in[6];
    const float* W2  = (const float*)d_in[7];
    const float* b2  = (const float*)d_in[8];
    const float* Wv2 = (const float*)d_in[11];
    const float* Wo2 = (const float*)d_in[12];
    const float* g2  = (const float*)d_in[13];
    const float* be2 = (const float*)d_in[14];
    const float* Wv3 = (const float*)d_in[17];
    const float* Wo3 = (const float*)d_in[18];
    const float* g3  = (const float*)d_in[19];
    const float* be3 = (const float*)d_in[20];
    const float* Wf1 = (const float*)d_in[21];
    const float* bf1 = (const float*)d_in[22];
    const float* Wf2 = (const float*)d_in[23];
    const float* bf2 = (const float*)d_in[24];

    prep_kernel<<<(W1RN * W1SW + 255) / 256, 256>>>(W1);

    cudaFuncSetAttribute(gnn_fused_kernel,
                         cudaFuncAttributeMaxDynamicSharedMemorySize,
                         K_BYTES);
    gnn_fused_kernel<<<NGRAPH, BLK, K_BYTES>>>(
        feat, edge_src, self_feat, x3d,
        b1, W2, b2,
        Wv2, Wo2, g2, be2,
        Wv3, Wo3, g3, be3,
        Wf1, bf1, Wf2, bf2,
        (float*)d_out);
}

// round 11
// speedup vs baseline: 2.3507x; 1.1947x over previous
#include <cuda_runtime.h>
#include <cuda_bf16.h>
#include <cstdint>

#define NPG   100
#define DEG   16
#define BLK   256
#define NGRAPH 512
#define MSW   60           // M/h1 bf16-pair word stride (banks 28qg+tig distinct)
#define WSW   58           // W1/W2 bf16-pair word stride (proven conflict-free)

// packed bf16 weights, produced by prep kernel
__device__ uint32_t W1b_g[104 * WSW];
__device__ uint32_t W2b_g[24 * WSW];

// ---------------- helpers ----------------
__device__ __forceinline__ void mma_bf16(float* c, const uint32_t* a,
                                         uint32_t b0, uint32_t b1) {
    asm volatile("mma.sync.aligned.m16n8k16.row.col.f32.bf16.bf16.f32 "
                 "{%0,%1,%2,%3}, {%4,%5,%6,%7}, {%8,%9}, {%0,%1,%2,%3};"
                 : "+f"(c[0]), "+f"(c[1]), "+f"(c[2]), "+f"(c[3])
                 : "r"(a[0]), "r"(a[1]), "r"(a[2]), "r"(a[3]),
                   "r"(b0), "r"(b1));
}
__device__ __forceinline__ uint32_t pack_bf(float x, float y) {
    __nv_bfloat16 a = __float2bfloat16(x), b = __float2bfloat16(y);
    return (uint32_t)*(uint16_t*)&a | ((uint32_t)*(uint16_t*)&b << 16);
}

// ====================== prep: W1/W2 -> packed bf16 pairs (zero-padded) ======================
__global__ void prep_kernel(const float* __restrict__ W1,
                            const float* __restrict__ W2) {
    int i = blockIdx.x * blockDim.x + threadIdx.x;
    if (i < 104 * WSW) {
        int n = i / WSW, w = i % WSW;
        float v0 = (n < 100 && 2 * w < 100)     ? W1[n * 100 + 2 * w]     : 0.f;
        float v1 = (n < 100 && 2 * w + 1 < 100) ? W1[n * 100 + 2 * w + 1] : 0.f;
        W1b_g[i] = pack_bf(v0, v1);
    } else if (i < 104 * WSW + 24 * WSW) {
        int j = i - 104 * WSW;
        int n = j / WSW, w = j % WSW;
        float v0 = (n < 20 && 2 * w < 100)     ? W2[n * 100 + 2 * w]     : 0.f;
        float v1 = (n < 20 && 2 * w + 1 < 100) ? W2[n * 100 + 2 * w + 1] : 0.f;
        W2b_g[j] = pack_bf(v0, v1);
    }
}

// ====================== fused main kernel ======================
// smem byte offsets
#define B_M    0                 // [112][60] u32 packed bf16: M -> h1 in place
#define B_W1   26880             // [104][58] u32 packed bf16 W1
#define B_W2   51008             // [24][58]  u32 packed bf16 W2
#define B_ST   56576             // [100][20] f32 sT
#define B_B1   64576             // [100] f32
#define B_B2   64976             // [20]
#define B_HG   65056             // [20]
#define B_Z2   65136             // [20]
#define B_Z3   65216             // [20]
#define B_V2S  65296             // [32]
#define B_V3S  65424             // [32]
#define B_SRC  65552             // [1600] bytes
#define K_BYTES 67152

__global__ __launch_bounds__(BLK, 3)
void gnn_fused_kernel(const float* __restrict__ feat,
                      const int*   __restrict__ edge_src,
                      const float* __restrict__ self_feat,
                      const float* __restrict__ x3d,
                      const float* __restrict__ b1,
                      const float* __restrict__ b2,
                      const float* __restrict__ Wv2, const float* __restrict__ Wo2,
                      const float* __restrict__ g2,  const float* __restrict__ be2,
                      const float* __restrict__ Wv3, const float* __restrict__ Wo3,
                      const float* __restrict__ g3,  const float* __restrict__ be3,
                      const float* __restrict__ Wf1, const float* __restrict__ bf1,
                      const float* __restrict__ Wf2, const float* __restrict__ bf2,
                      float* __restrict__ out)
{
    extern __shared__ unsigned char sm[];
    uint32_t* sMw = (uint32_t*)(sm + B_M);     // M -> h1 in place (packed bf16)
    uint32_t* sW1 = (uint32_t*)(sm + B_W1);
    uint32_t* sW2 = (uint32_t*)(sm + B_W2);
    float* sT  = (float*)(sm + B_ST);
    float* sB1 = (float*)(sm + B_B1);
    float* sB2 = (float*)(sm + B_B2);
    float* shg = (float*)(sm + B_HG);
    unsigned char* sSrc = sm + B_SRC;

    const int g    = blockIdx.x;
    const int tid  = threadIdx.x;
    const int lane = tid & 31;
    const int warp = tid >> 5;
    const int qg   = lane >> 2;
    const int tig  = lane & 3;

    // ---- phase 0: zero M tile; stage W1b, W2b, biases, edge bytes ----
    {
        uint4 z = make_uint4(0, 0, 0, 0);
        uint4* mz = (uint4*)sMw;
        for (int i = tid; i < 112 * MSW / 4; i += BLK) mz[i] = z;

        const uint2* gw1 = (const uint2*)W1b_g;
        uint2* sw1 = (uint2*)sW1;
        for (int i = tid; i < 104 * WSW / 2; i += BLK) sw1[i] = gw1[i];
        const uint2* gw2 = (const uint2*)W2b_g;
        uint2* sw2 = (uint2*)sW2;
        for (int i = tid; i < 24 * WSW / 2; i += BLK) sw2[i] = gw2[i];

        if (tid < 100) sB1[tid] = b1[tid];
        if (tid < 20)  sB2[tid] = b2[tid];
        if (tid < 20)  shg[tid] = 0.f;
        const int* es = edge_src + (size_t)g * NPG * DEG;
        const int base = g * NPG;
        for (int i = tid; i < NPG * DEG; i += BLK)
            sSrc[i] = (unsigned char)(es[i] - base);
    }
    __syncthreads();   // S0

    // ---- phase G: M = mean_e feat[src]; accumulate fp32, store packed bf16 ----
    {
        const float4* Fg = (const float4*)(feat + (size_t)g * NPG * 100);
        const bool act = (lane < 25);
        for (int n = warp; n < NPG; n += 8) {
            const uint4 w = *(const uint4*)(sSrc + n * DEG);
            if (act) {
                float4 a0 = make_float4(0.f, 0.f, 0.f, 0.f);
                float4 a1 = a0, a2 = a0, a3 = a0;
                #pragma unroll
                for (int b = 0; b < 4; b++) {
                    int s0 = (w.x >> (8 * b)) & 0xff;
                    int s1 = (w.y >> (8 * b)) & 0xff;
                    int s2 = (w.z >> (8 * b)) & 0xff;
                    int s3 = (w.w >> (8 * b)) & 0xff;
                    float4 v0 = __ldg(Fg + s0 * 25 + lane);
                    float4 v1 = __ldg(Fg + s1 * 25 + lane);
                    float4 v2 = __ldg(Fg + s2 * 25 + lane);
                    float4 v3 = __ldg(Fg + s3 * 25 + lane);
                    a0.x += v0.x; a0.y += v0.y; a0.z += v0.z; a0.w += v0.w;
                    a1.x += v1.x; a1.y += v1.y; a1.z += v1.z; a1.w += v1.w;
                    a2.x += v2.x; a2.y += v2.y; a2.z += v2.z; a2.w += v2.w;
                    a3.x += v3.x; a3.y += v3.y; a3.z += v3.z; a3.w += v3.w;
                }
                uint2 st;
                st.x = pack_bf((a0.x + a1.x + a2.x + a3.x) * (1.f / DEG),
                               (a0.y + a1.y + a2.y + a3.y) * (1.f / DEG));
                st.y = pack_bf((a0.z + a1.z + a2.z + a3.z) * (1.f / DEG),
                               (a0.w + a1.w + a2.w + a3.w) * (1.f / DEG));
                *(uint2*)(sMw + n * MSW + 2 * lane) = st;
            }
        }
    }
    __syncthreads();   // S1

    // ---- phase A+C (warps 0-6): h1 = relu(M@W1^T + b1); sT = h1@W2^T ----
    // All out-of-range rows/k-words in the M tile are ZERO -> no fragment guards.
    if (warp < 7) {
        const int m0 = warp * 16;
        const int r0l = m0 + qg, r1l = m0 + 8 + qg;
        uint32_t a[7][4];

        // A-fragments from M (own strip only)
        #pragma unroll
        for (int kt = 0; kt < 7; kt++) {
            const int i0 = r0l * MSW + kt * 8 + tig;
            const int i1 = r1l * MSW + kt * 8 + tig;
            a[kt][0] = sMw[i0];     a[kt][1] = sMw[i1];
            a[kt][2] = sMw[i0 + 4]; a[kt][3] = sMw[i1 + 4];
        }
        // GEMM1: 13 n-tiles, h1 packed back in place (same rows)
        #pragma unroll 1
        for (int nt = 0; nt < 13; nt++) {
            float acc[4] = {0.f, 0.f, 0.f, 0.f};
            #pragma unroll
            for (int kt = 0; kt < 7; kt++) {
                const int idx = (nt * 8 + qg) * WSW + kt * 8 + tig;
                mma_bf16(acc, a[kt], sW1[idx], sW1[idx + 4]);
            }
            const int col = nt * 8 + 2 * tig;
            if (col < 100) {
                const float bx = sB1[col], by = sB1[col + 1];
                if (r0l < 100)
                    sMw[r0l * MSW + (col >> 1)] =
                        pack_bf(fmaxf(acc[0] + bx, 0.f), fmaxf(acc[1] + by, 0.f));
                if (r1l < 100)
                    sMw[r1l * MSW + (col >> 1)] =
                        pack_bf(fmaxf(acc[2] + bx, 0.f), fmaxf(acc[3] + by, 0.f));
            }
        }
        __syncwarp();   // h1 strip visible within warp (only own strip is read)

        // reload fragments from h1 (same addresses; pad words still zero)
        #pragma unroll
        for (int kt = 0; kt < 7; kt++) {
            const int i0 = r0l * MSW + kt * 8 + tig;
            const int i1 = r1l * MSW + kt * 8 + tig;
            a[kt][0] = sMw[i0];     a[kt][1] = sMw[i1];
            a[kt][2] = sMw[i0 + 4]; a[kt][3] = sMw[i1 + 4];
        }
        // GEMM2: 3 n-tiles -> sT fp32 [100][20]
        #pragma unroll
        for (int nt = 0; nt < 3; nt++) {
            float acc[4] = {0.f, 0.f, 0.f, 0.f};
            #pragma unroll
            for (int kt = 0; kt < 7; kt++) {
                const int idx = (nt * 8 + qg) * WSW + kt * 8 + tig;
                mma_bf16(acc, a[kt], sW2[idx], sW2[idx + 4]);
            }
            const int col = nt * 8 + 2 * tig;
            if (col < 20) {
                if (r0l < 100)
                    *(float2*)(sT + r0l * 20 + col) = make_float2(acc[0], acc[1]);
                if (r1l < 100)
                    *(float2*)(sT + r1l * 20 + col) = make_float2(acc[2], acc[3]);
            }
        }
    } else {
        // warp 7: z2 = Wo2 @ (Wv2 @ self_feat[g]);  z3 = Wo3 @ (Wv3 @ x3d[g])
        float* vs2 = (float*)(sm + B_V2S);
        {
            const float4* xr = (const float4*)(self_feat + (size_t)g * 200);
            const float4* wr = (const float4*)(Wv2 + lane * 200);
            float acc = 0.f;
            #pragma unroll 5
            for (int p = 0; p < 50; p++) {
                float4 av = wr[p], bv = xr[p];
                acc += av.x * bv.x + av.y * bv.y + av.z * bv.z + av.w * bv.w;
            }
            vs2[lane] = acc;
        }
        __syncwarp();
        if (lane < 20) {
            const float* wo = Wo2 + lane * 32;
            float z = 0.f;
            #pragma unroll
            for (int j = 0; j < 32; j++) z += wo[j] * vs2[j];
            ((float*)(sm + B_Z2))[lane] = z;
        }
        __syncwarp();
        float* vs3 = (float*)(sm + B_V3S);
        {
            const float4* xr = (const float4*)(x3d + (size_t)g * 100);
            const float4* wr = (const float4*)(Wv3 + lane * 100);
            float acc = 0.f;
            #pragma unroll 5
            for (int p = 0; p < 25; p++) {
                float4 av = wr[p], bv = xr[p];
                acc += av.x * bv.x + av.y * bv.y + av.z * bv.z + av.w * bv.w;
            }
            vs3[lane] = acc;
        }
        __syncwarp();
        if (lane < 20) {
            const float* wo = Wo3 + lane * 32;
            float z = 0.f;
            #pragma unroll
            for (int j = 0; j < 32; j++) z += wo[j] * vs3[j];
            ((float*)(sm + B_Z3))[lane] = z;
        }
    }
    __syncthreads();   // S3: sT complete

    // ---- phase D: h2 = relu(mean_e sT[src] + b2); hg = sum_n h2 ----
    if (lane < 20) {
        float hgacc = 0.f;
        for (int n = warp; n < NPG; n += 8) {
            const unsigned char* sp = sSrc + n * DEG;
            float a = 0.f;
            #pragma unroll
            for (int e = 0; e < DEG; e++)
                a += sT[sp[e] * 20 + lane];
            hgacc += fmaxf(a * (1.f / DEG) + sB2[lane], 0.f);
        }
        atomicAdd(&shg[lane], hgacc);
    }
    __syncthreads();   // S5

    // ---- tail (warp 0): hg + z2 -> LN -> + z3 -> LN -> MLP ----
    if (warp == 0) {
        const float* z2 = (const float*)(sm + B_Z2);
        const float* z3 = (const float*)(sm + B_Z3);
        float* sVec = (float*)(sm + B_V2S);

        float y = 0.f;
        if (lane < 20) y = shg[lane] * (1.f / NPG) + z2[lane];
        float s = y;
        #pragma unroll
        for (int o = 16; o; o >>= 1) s += __shfl_xor_sync(0xffffffffu, s, o);
        float mu = s * (1.f / 20.f);
        float dd = (lane < 20) ? (y - mu) : 0.f;
        float vv = dd * dd;
        #pragma unroll
        for (int o = 16; o; o >>= 1) vv += __shfl_xor_sync(0xffffffffu, vv, o);
        float hg1 = 0.f;
        if (lane < 20)
            hg1 = dd * rsqrtf(vv * (1.f / 20.f) + 1e-5f) * g2[lane] + be2[lane];

        float y2 = (lane < 20) ? (hg1 + z3[lane]) : 0.f;
        float s2 = y2;
        #pragma unroll
        for (int o = 16; o; o >>= 1) s2 += __shfl_xor_sync(0xffffffffu, s2, o);
        float mu2 = s2 * (1.f / 20.f);
        float d2 = (lane < 20) ? (y2 - mu2) : 0.f;
        float v2s = d2 * d2;
        #pragma unroll
        for (int o = 16; o; o >>= 1) v2s += __shfl_xor_sync(0xffffffffu, v2s, o);
        float hg2 = 0.f;
        if (lane < 20)
            hg2 = d2 * rsqrtf(v2s * (1.f / 20.f) + 1e-5f) * g3[lane] + be3[lane];

        __syncwarp();
        if (lane < 20) sVec[lane] = hg2;
        __syncwarp();

        float f = 0.f;
        if (lane < 10) {
            const float* wf = Wf1 + lane * 20;
            float a = bf1[lane];
            #pragma unroll
            for (int k = 0; k < 20; k++) a += wf[k] * sVec[k];
            f = fmaxf(a, 0.f) * Wf2[lane];
        }
        #pragma unroll
        for (int o = 16; o; o >>= 1) f += __shfl_xor_sync(0xffffffffu, f, o);
        if (lane == 0) out[g] = f + bf2[0];
    }
}

// ============================ launch ============================
extern "C" void kernel_launch(void* const* d_in, const int* in_sizes, int n_in,
                              void* d_out, int out_size) {
    const float* feat      = (const float*)d_in[0];
    const int*   edge_src  = (const int*)  d_in[1];
    // d_in[2] = edge_dst: repeat(arange(N), DEG) by construction — implicit
    const float* self_feat = (const float*)d_in[3];
    const float* x3d       = (const float*)d_in[4];
    const float* W1  = (const float*)d_in[5];
    const float* b1  = (const float*)d_in[6];
    const float* W2  = (const float*)d_in[7];
    const float* b2  = (const float*)d_in[8];
    const float* Wv2 = (const float*)d_in[11];
    const float* Wo2 = (const float*)d_in[12];
    const float* g2  = (const float*)d_in[13];
    const float* be2 = (const float*)d_in[14];
    const float* Wv3 = (const float*)d_in[17];
    const float* Wo3 = (const float*)d_in[18];
    const float* g3  = (const float*)d_in[19];
    const float* be3 = (const float*)d_in[20];
    const float* Wf1 = (const float*)d_in[21];
    const float* bf1 = (const float*)d_in[22];
    const float* Wf2 = (const float*)d_in[23];
    const float* bf2 = (const float*)d_in[24];

    prep_kernel<<<(104 * WSW + 24 * WSW + 255) / 256, 256>>>(W1, W2);

    cudaFuncSetAttribute(gnn_fused_kernel,
                         cudaFuncAttributeMaxDynamicSharedMemorySize,
                         K_BYTES);
    gnn_fused_kernel<<<NGRAPH, BLK, K_BYTES>>>(
        feat, edge_src, self_feat, x3d,
        b1, b2,
        Wv2, Wo2, g2, be2,
        Wv3, Wo3, g3, be3,
        Wf1, bf1, Wf2, bf2,
        (float*)d_out);
}

// round 12
// speedup vs baseline: 2.4383x; 1.0373x over previous
#include <cuda_runtime.h>
#include <cuda_bf16.h>
#include <cstdint>

#define NPG   100
#define DEG   16
#define BLK   256
#define NGRAPH 512
#define TSW   60           // F/Adj/PT/sTT word stride (banks 28qg+tig distinct)
#define WSW   58           // W1/W2 word stride (proven conflict-free)

// packed bf16 weights, produced by prep kernel
__device__ uint32_t W1b_g[104 * WSW];
__device__ uint32_t W2b_g[24 * WSW];

// ---------------- helpers ----------------
__device__ __forceinline__ void mma_bf16(float* c, const uint32_t* a,
                                         uint32_t b0, uint32_t b1) {
    asm volatile("mma.sync.aligned.m16n8k16.row.col.f32.bf16.bf16.f32 "
                 "{%0,%1,%2,%3}, {%4,%5,%6,%7}, {%8,%9}, {%0,%1,%2,%3};"
                 : "+f"(c[0]), "+f"(c[1]), "+f"(c[2]), "+f"(c[3])
                 : "r"(a[0]), "r"(a[1]), "r"(a[2]), "r"(a[3]),
                   "r"(b0), "r"(b1));
}
__device__ __forceinline__ uint32_t pack_bf(float x, float y) {
    __nv_bfloat16 a = __float2bfloat16(x), b = __float2bfloat16(y);
    return (uint32_t)*(uint16_t*)&a | ((uint32_t)*(uint16_t*)&b << 16);
}

// ====================== prep: W1/W2 -> packed bf16 pairs (zero-padded) ======================
__global__ void prep_kernel(const float* __restrict__ W1,
                            const float* __restrict__ W2) {
    int i = blockIdx.x * blockDim.x + threadIdx.x;
    if (i < 104 * WSW) {
        int n = i / WSW, w = i % WSW;
        float v0 = (n < 100 && 2 * w < 100)     ? W1[n * 100 + 2 * w]     : 0.f;
        float v1 = (n < 100 && 2 * w + 1 < 100) ? W1[n * 100 + 2 * w + 1] : 0.f;
        W1b_g[i] = pack_bf(v0, v1);
    } else if (i < 104 * WSW + 24 * WSW) {
        int j = i - 104 * WSW;
        int n = j / WSW, w = j % WSW;
        float v0 = (n < 20 && 2 * w < 100)     ? W2[n * 100 + 2 * w]     : 0.f;
        float v1 = (n < 20 && 2 * w + 1 < 100) ? W2[n * 100 + 2 * w + 1] : 0.f;
        W2b_g[j] = pack_bf(v0, v1);
    }
}

// ====================== fused main kernel ======================
// smem byte offsets
#define B_F    0                 // [100][60] u32 bf16: F -> h1 in place (zeroed)
#define B_ADJ  24000             // [100][60] u32 bf16 adjacency/16 (zeroed)
#define B_PT   48000             // [104][60] u32 bf16 P^T
#define B_W1   72960             // [104][58] u32 bf16 W1
#define B_W2   97088             // [24][58]  u32 bf16 W2
#define B_STT  102656            // [24][60]  u32 bf16 sT^T
#define B_B1   108416            // [100] f32
#define B_B2   108816            // [20]
#define B_HG   108896            // [20]
#define B_Z2   108976            // [20]
#define B_Z3   109056            // [20]
#define B_V2S  109136            // [32]
#define B_V3S  109264            // [32]
#define K_BYTES 109392

__global__ __launch_bounds__(BLK, 2)
void gnn_fused_kernel(const float* __restrict__ feat,
                      const int*   __restrict__ edge_src,
                      const float* __restrict__ self_feat,
                      const float* __restrict__ x3d,
                      const float* __restrict__ b1,
                      const float* __restrict__ b2,
                      const float* __restrict__ Wv2, const float* __restrict__ Wo2,
                      const float* __restrict__ g2,  const float* __restrict__ be2,
                      const float* __restrict__ Wv3, const float* __restrict__ Wo3,
                      const float* __restrict__ g3,  const float* __restrict__ be3,
                      const float* __restrict__ Wf1, const float* __restrict__ bf1,
                      const float* __restrict__ Wf2, const float* __restrict__ bf2,
                      float* __restrict__ out)
{
    extern __shared__ unsigned char sm[];
    uint32_t* sF   = (uint32_t*)(sm + B_F);     // F -> h1 in place
    uint32_t* sAdj = (uint32_t*)(sm + B_ADJ);
    uint32_t* sPT  = (uint32_t*)(sm + B_PT);
    uint32_t* sW1  = (uint32_t*)(sm + B_W1);
    uint32_t* sW2  = (uint32_t*)(sm + B_W2);
    uint32_t* sSTT = (uint32_t*)(sm + B_STT);
    float* sB1 = (float*)(sm + B_B1);
    float* sB2 = (float*)(sm + B_B2);
    float* shg = (float*)(sm + B_HG);

    const int g    = blockIdx.x;
    const int tid  = threadIdx.x;
    const int lane = tid & 31;
    const int warp = tid >> 5;
    const int qg   = lane >> 2;
    const int tig  = lane & 3;

    // ---- phase 0: zero F+Adj; stage W1b, W2b, biases ----
    {
        uint4 z = make_uint4(0, 0, 0, 0);
        uint4* mz = (uint4*)sF;            // F and Adj are contiguous: 48000 B
        for (int i = tid; i < 48000 / 16; i += BLK) mz[i] = z;

        const uint2* gw1 = (const uint2*)W1b_g;
        uint2* sw1 = (uint2*)sW1;
        for (int i = tid; i < 104 * WSW / 2; i += BLK) sw1[i] = gw1[i];
        const uint2* gw2 = (const uint2*)W2b_g;
        uint2* sw2 = (uint2*)sW2;
        for (int i = tid; i < 24 * WSW / 2; i += BLK) sw2[i] = gw2[i];

        if (tid < 100) sB1[tid] = b1[tid];
        if (tid < 20)  sB2[tid] = b2[tid];
        if (tid < 20)  shg[tid] = 0.f;
    }
    __syncthreads();   // S0

    // ---- phase 1: pack F; build adjacency ----
    {
        const float4* Fg = (const float4*)(feat + (size_t)g * NPG * 100);
        for (int i = tid; i < 2500; i += BLK) {
            float4 v = Fg[i];
            int s = i / 25, w = (i % 25) * 2;
            sF[s * TSW + w]     = pack_bf(v.x, v.y);
            sF[s * TSW + w + 1] = pack_bf(v.z, v.w);
        }
        if (tid < 100) {
            const int4* es = (const int4*)(edge_src + (size_t)g * NPG * DEG + tid * DEG);
            const int base = g * NPG;
            __nv_bfloat16* arow = (__nv_bfloat16*)sAdj + tid * 2 * TSW;
            #pragma unroll
            for (int q = 0; q < 4; q++) {
                int4 e = es[q];
                int s0 = e.x - base, s1 = e.y - base, s2 = e.z - base, s3 = e.w - base;
                arow[s0] = __float2bfloat16(__bfloat162float(arow[s0]) + 0.0625f);
                arow[s1] = __float2bfloat16(__bfloat162float(arow[s1]) + 0.0625f);
                arow[s2] = __float2bfloat16(__bfloat162float(arow[s2]) + 0.0625f);
                arow[s3] = __float2bfloat16(__bfloat162float(arow[s3]) + 0.0625f);
            }
        }
    }
    __syncthreads();   // S1

    const int m0  = warp * 16;
    const int r0  = m0 + qg, r1 = m0 + 8 + qg;
    const int cr0 = (r0 > 99) ? 99 : r0;
    const int cr1 = (r1 > 99) ? 99 : r1;

    // ---- phase 2 (warps 0-6): P = F @ W1^T, write P^T; warp 7: z2/z3 ----
    if (warp < 7) {
        uint32_t a[7][4];
        #pragma unroll
        for (int kt = 0; kt < 7; kt++) {
            const int i0 = cr0 * TSW + kt * 8 + tig;
            const int i1 = cr1 * TSW + kt * 8 + tig;
            a[kt][0] = sF[i0];     a[kt][1] = sF[i1];
            a[kt][2] = sF[i0 + 4]; a[kt][3] = sF[i1 + 4];
        }
        __nv_bfloat16* PT = (__nv_bfloat16*)sPT;
        #pragma unroll 1
        for (int nt = 0; nt < 13; nt++) {
            float acc[4] = {0.f, 0.f, 0.f, 0.f};
            #pragma unroll
            for (int kt = 0; kt < 7; kt++) {
                const int idx = (nt * 8 + qg) * WSW + kt * 8 + tig;
                mma_bf16(acc, a[kt], sW1[idx], sW1[idx + 4]);
            }
            const int col = nt * 8 + 2 * tig;   // <= 103, rows allocated
            // unguarded transposed store: r<=111 < 120 entries; pad cols pair
            // with zero Adj k-words downstream, so junk is annihilated
            PT[col * 2 * TSW + r0]       = __float2bfloat16(acc[0]);
            PT[(col + 1) * 2 * TSW + r0] = __float2bfloat16(acc[1]);
            PT[col * 2 * TSW + r1]       = __float2bfloat16(acc[2]);
            PT[(col + 1) * 2 * TSW + r1] = __float2bfloat16(acc[3]);
        }
    } else {
        // warp 7: z2 = Wo2 @ (Wv2 @ self_feat[g]);  z3 = Wo3 @ (Wv3 @ x3d[g])
        float* vs2 = (float*)(sm + B_V2S);
        {
            const float4* xr = (const float4*)(self_feat + (size_t)g * 200);
            const float4* wr = (const float4*)(Wv2 + lane * 200);
            float acc = 0.f;
            #pragma unroll 5
            for (int p = 0; p < 50; p++) {
                float4 av = wr[p], bv = xr[p];
                acc += av.x * bv.x + av.y * bv.y + av.z * bv.z + av.w * bv.w;
            }
            vs2[lane] = acc;
        }
        __syncwarp();
        if (lane < 20) {
            const float* wo = Wo2 + lane * 32;
            float z = 0.f;
            #pragma unroll
            for (int j = 0; j < 32; j++) z += wo[j] * vs2[j];
            ((float*)(sm + B_Z2))[lane] = z;
        }
        __syncwarp();
        float* vs3 = (float*)(sm + B_V3S);
        {
            const float4* xr = (const float4*)(x3d + (size_t)g * 100);
            const float4* wr = (const float4*)(Wv3 + lane * 100);
            float acc = 0.f;
            #pragma unroll 5
            for (int p = 0; p < 25; p++) {
                float4 av = wr[p], bv = xr[p];
                acc += av.x * bv.x + av.y * bv.y + av.z * bv.z + av.w * bv.w;
            }
            vs3[lane] = acc;
        }
        __syncwarp();
        if (lane < 20) {
            const float* wo = Wo3 + lane * 32;
            float z = 0.f;
            #pragma unroll
            for (int j = 0; j < 32; j++) z += wo[j] * vs3[j];
            ((float*)(sm + B_Z3))[lane] = z;
        }
    }
    __syncthreads();   // S2: P^T ready

    // ---- phase 3 (warps 0-6): h1 = relu(Adj @ P + b1) -> F tile; sT = h1 @ W2^T -> sT^T ----
    if (warp < 7) {
        uint32_t a[7][4];
        #pragma unroll
        for (int kt = 0; kt < 7; kt++) {
            const int i0 = cr0 * TSW + kt * 8 + tig;
            const int i1 = cr1 * TSW + kt * 8 + tig;
            a[kt][0] = sAdj[i0];     a[kt][1] = sAdj[i1];
            a[kt][2] = sAdj[i0 + 4]; a[kt][3] = sAdj[i1 + 4];
        }
        // h1 over F tile (F not read by this phase; own strip only)
        #pragma unroll 1
        for (int nt = 0; nt < 13; nt++) {
            float acc[4] = {0.f, 0.f, 0.f, 0.f};
            #pragma unroll
            for (int kt = 0; kt < 7; kt++) {
                const int idx = (nt * 8 + qg) * TSW + kt * 8 + tig;
                mma_bf16(acc, a[kt], sPT[idx], sPT[idx + 4]);
            }
            const int col = nt * 8 + 2 * tig;
            if (col < 100) {
                const float bx = sB1[col], by = sB1[col + 1];
                if (r0 < 100)
                    sF[r0 * TSW + (col >> 1)] =
                        pack_bf(fmaxf(acc[0] + bx, 0.f), fmaxf(acc[1] + by, 0.f));
                if (r1 < 100)
                    sF[r1 * TSW + (col >> 1)] =
                        pack_bf(fmaxf(acc[2] + bx, 0.f), fmaxf(acc[3] + by, 0.f));
            }
        }
        __syncwarp();   // own h1 strip visible

        // GEMM2: sT = h1 @ W2^T -> transposed bf16 store
        uint32_t h[7][4];
        #pragma unroll
        for (int kt = 0; kt < 7; kt++) {
            const int i0 = cr0 * TSW + kt * 8 + tig;
            const int i1 = cr1 * TSW + kt * 8 + tig;
            h[kt][0] = sF[i0];     h[kt][1] = sF[i1];
            h[kt][2] = sF[i0 + 4]; h[kt][3] = sF[i1 + 4];
        }
        __nv_bfloat16* STT = (__nv_bfloat16*)sSTT;
        #pragma unroll
        for (int nt = 0; nt < 3; nt++) {
            float acc[4] = {0.f, 0.f, 0.f, 0.f};
            #pragma unroll
            for (int kt = 0; kt < 7; kt++) {
                const int idx = (nt * 8 + qg) * WSW + kt * 8 + tig;
                mma_bf16(acc, h[kt], sW2[idx], sW2[idx + 4]);
            }
            const int col = nt * 8 + 2 * tig;   // <= 23, rows allocated
            STT[col * 2 * TSW + r0]       = __float2bfloat16(acc[0]);
            STT[(col + 1) * 2 * TSW + r0] = __float2bfloat16(acc[1]);
            STT[col * 2 * TSW + r1]       = __float2bfloat16(acc[2]);
            STT[(col + 1) * 2 * TSW + r1] = __float2bfloat16(acc[3]);
        }
    }
    __syncthreads();   // S3: sT^T ready

    // ---- phase 4 (warps 0-6): h2 = relu(Adj @ sT + b2); hg accum ----
    if (warp < 7) {
        uint32_t a[7][4];
        #pragma unroll
        for (int kt = 0; kt < 7; kt++) {
            const int i0 = cr0 * TSW + kt * 8 + tig;
            const int i1 = cr1 * TSW + kt * 8 + tig;
            a[kt][0] = sAdj[i0];     a[kt][1] = sAdj[i1];
            a[kt][2] = sAdj[i0 + 4]; a[kt][3] = sAdj[i1 + 4];
        }
        #pragma unroll
        for (int nt = 0; nt < 3; nt++) {
            float acc[4] = {0.f, 0.f, 0.f, 0.f};
            #pragma unroll
            for (int kt = 0; kt < 7; kt++) {
                const int idx = (nt * 8 + qg) * TSW + kt * 8 + tig;
                mma_bf16(acc, a[kt], sSTT[idx], sSTT[idx + 4]);
            }
            const int col = nt * 8 + 2 * tig;
            if (col < 20) {
                const float bx = sB2[col], by = sB2[col + 1];
                float add0 = (r0 < 100 ? fmaxf(acc[0] + bx, 0.f) : 0.f)
                           + (r1 < 100 ? fmaxf(acc[2] + bx, 0.f) : 0.f);
                float add1 = (r0 < 100 ? fmaxf(acc[1] + by, 0.f) : 0.f)
                           + (r1 < 100 ? fmaxf(acc[3] + by, 0.f) : 0.f);
                atomicAdd(shg + col, add0);
                atomicAdd(shg + col + 1, add1);
            }
        }
    }
    __syncthreads();   // S4

    // ---- tail (warp 0): hg + z2 -> LN -> + z3 -> LN -> MLP ----
    if (warp == 0) {
        const float* z2 = (const float*)(sm + B_Z2);
        const float* z3 = (const float*)(sm + B_Z3);
        float* sVec = (float*)(sm + B_V2S);

        float y = 0.f;
        if (lane < 20) y = shg[lane] * (1.f / NPG) + z2[lane];
        float s = y;
        #pragma unroll
        for (int o = 16; o; o >>= 1) s += __shfl_xor_sync(0xffffffffu, s, o);
        float mu = s * (1.f / 20.f);
        float dd = (lane < 20) ? (y - mu) : 0.f;
        float vv = dd * dd;
        #pragma unroll
        for (int o = 16; o; o >>= 1) vv += __shfl_xor_sync(0xffffffffu, vv, o);
        float hg1 = 0.f;
        if (lane < 20)
            hg1 = dd * rsqrtf(vv * (1.f / 20.f) + 1e-5f) * g2[lane] + be2[lane];

        float y2 = (lane < 20) ? (hg1 + z3[lane]) : 0.f;
        float s2 = y2;
        #pragma unroll
        for (int o = 16; o; o >>= 1) s2 += __shfl_xor_sync(0xffffffffu, s2, o);
        float mu2 = s2 * (1.f / 20.f);
        float d2 = (lane < 20) ? (y2 - mu2) : 0.f;
        float v2s = d2 * d2;
        #pragma unroll
        for (int o = 16; o; o >>= 1) v2s += __shfl_xor_sync(0xffffffffu, v2s, o);
        float hg2 = 0.f;
        if (lane < 20)
            hg2 = d2 * rsqrtf(v2s * (1.f / 20.f) + 1e-5f) * g3[lane] + be3[lane];

        __syncwarp();
        if (lane < 20) sVec[lane] = hg2;
        __syncwarp();

        float f = 0.f;
        if (lane < 10) {
            const float* wf = Wf1 + lane * 20;
            float a = bf1[lane];
            #pragma unroll
            for (int k = 0; k < 20; k++) a += wf[k] * sVec[k];
            f = fmaxf(a, 0.f) * Wf2[lane];
        }
        #pragma unroll
        for (int o = 16; o; o >>= 1) f += __shfl_xor_sync(0xffffffffu, f, o);
        if (lane == 0) out[g] = f + bf2[0];
    }
}

// ============================ launch ============================
extern "C" void kernel_launch(void* const* d_in, const int* in_sizes, int n_in,
                              void* d_out, int out_size) {
    const float* feat      = (const float*)d_in[0];
    const int*   edge_src  = (const int*)  d_in[1];
    // d_in[2] = edge_dst: repeat(arange(N), DEG) by construction — implicit
    const float* self_feat = (const float*)d_in[3];
    const float* x3d       = (const float*)d_in[4];
    const float* W1  = (const float*)d_in[5];
    const float* b1  = (const float*)d_in[6];
    const float* W2  = (const float*)d_in[7];
    const float* b2  = (const float*)d_in[8];
    const float* Wv2 = (const float*)d_in[11];
    const float* Wo2 = (const float*)d_in[12];
    const float* g2  = (const float*)d_in[13];
    const float* be2 = (const float*)d_in[14];
    const float* Wv3 = (const float*)d_in[17];
    const float* Wo3 = (const float*)d_in[18];
    const float* g3  = (const float*)d_in[19];
    const float* be3 = (const float*)d_in[20];
    const float* Wf1 = (const float*)d_in[21];
    const float* bf1 = (const float*)d_in[22];
    const float* Wf2 = (const float*)d_in[23];
    const float* bf2 = (const float*)d_in[24];

    prep_kernel<<<(104 * WSW + 24 * WSW + 255) / 256, 256>>>(W1, W2);

    cudaFuncSetAttribute(gnn_fused_kernel,
                         cudaFuncAttributeMaxDynamicSharedMemorySize,
                         K_BYTES);
    gnn_fused_kernel<<<NGRAPH, BLK, K_BYTES>>>(
        feat, edge_src, self_feat, x3d,
        b1, b2,
        Wv2, Wo2, g2, be2,
        Wv3, Wo3, g3, be3,
        Wf1, bf1, Wf2, bf2,
        (float*)d_out);
}

// round 16
// speedup vs baseline: 3.1250x; 1.2816x over previous
#include <cuda_runtime.h>
#include <cuda_bf16.h>
#include <cstdint>

#define NPG   100
#define DEG   16
#define BLK   256
#define NGRAPH 512
#define TSW   60           // tile/Adj/sTT word stride (banks 28qg+tig distinct)
#define WSW   58           // W1/W2 global word stride

// packed bf16 weights (zero-padded), produced by prep kernel
__device__ uint32_t W1b_g[112 * WSW];   // rows 100-111 zero
__device__ uint32_t W2b_g[32 * WSW];    // rows 20-31 zero

// ---------------- helpers ----------------
__device__ __forceinline__ void mma_bf16(float* c, const uint32_t* a,
                                         uint32_t b0, uint32_t b1) {
    asm volatile("mma.sync.aligned.m16n8k16.row.col.f32.bf16.bf16.f32 "
                 "{%0,%1,%2,%3}, {%4,%5,%6,%7}, {%8,%9}, {%0,%1,%2,%3};"
                 : "+f"(c[0]), "+f"(c[1]), "+f"(c[2]), "+f"(c[3])
                 : "r"(a[0]), "r"(a[1]), "r"(a[2]), "r"(a[3]),
                   "r"(b0), "r"(b1));
}
__device__ __forceinline__ uint32_t pack_bf(float x, float y) {
    __nv_bfloat16 a = __float2bfloat16(x), b = __float2bfloat16(y);
    return (uint32_t)*(uint16_t*)&a | ((uint32_t)*(uint16_t*)&b << 16);
}

// ====================== prep: W1/W2 -> packed bf16 pairs (zero-padded) ======================
__global__ void prep_kernel(const float* __restrict__ W1,
                            const float* __restrict__ W2) {
    int i = blockIdx.x * blockDim.x + threadIdx.x;
    if (i < 112 * WSW) {
        int n = i / WSW, w = i % WSW;
        float v0 = (n < 100 && 2 * w < 100)     ? W1[n * 100 + 2 * w]     : 0.f;
        float v1 = (n < 100 && 2 * w + 1 < 100) ? W1[n * 100 + 2 * w + 1] : 0.f;
        W1b_g[i] = pack_bf(v0, v1);
    } else if (i < 112 * WSW + 32 * WSW) {
        int j = i - 112 * WSW;
        int n = j / WSW, w = j % WSW;
        float v0 = (n < 20 && 2 * w < 100)     ? W2[n * 100 + 2 * w]     : 0.f;
        float v1 = (n < 20 && 2 * w + 1 < 100) ? W2[n * 100 + 2 * w + 1] : 0.f;
        W2b_g[j] = pack_bf(v0, v1);
    }
}

// ====================== fused main kernel ======================
// smem byte offsets
#define B_TILE 0                 // [104][60] u32 bf16: F -> P^T -> h1 (one tile)
#define B_ADJ  24960             // [100][60] u32 bf16 adjacency/16 (zeroed)
#define B_STT  48960             // [24][60]  u32 bf16 sT^T (zeroed)
#define B_B1   54720             // [100] f32
#define B_B2   55120             // [20]
#define B_HG   55200             // [20]
#define B_Z2   55280             // [20]
#define B_Z3   55360             // [20]
#define B_V2S  55440             // [32]
#define B_V3S  55568             // [32]
#define K_BYTES 55696

__global__ __launch_bounds__(BLK, 3)
void gnn_fused_kernel(const float* __restrict__ feat,
                      const int*   __restrict__ edge_src,
                      const float* __restrict__ self_feat,
                      const float* __restrict__ x3d,
                      const float* __restrict__ b1,
                      const float* __restrict__ b2,
                      const float* __restrict__ Wv2, const float* __restrict__ Wo2,
                      const float* __restrict__ g2,  const float* __restrict__ be2,
                      const float* __restrict__ Wv3, const float* __restrict__ Wo3,
                      const float* __restrict__ g3,  const float* __restrict__ be3,
                      const float* __restrict__ Wf1, const float* __restrict__ bf1,
                      const float* __restrict__ Wf2, const float* __restrict__ bf2,
                      float* __restrict__ out)
{
    extern __shared__ unsigned char sm[];
    uint32_t* sTile = (uint32_t*)(sm + B_TILE);
    uint32_t* sAdj  = (uint32_t*)(sm + B_ADJ);
    uint32_t* sSTT  = (uint32_t*)(sm + B_STT);
    float* sB1 = (float*)(sm + B_B1);
    float* sB2 = (float*)(sm + B_B2);
    float* shg = (float*)(sm + B_HG);

    const int g    = blockIdx.x;
    const int tid  = threadIdx.x;
    const int lane = tid & 31;
    const int warp = tid >> 5;
    const int qg   = lane >> 2;
    const int tig  = lane & 3;

    // ---- phase 0: zero tile+Adj+sTT; biases ----
    {
        uint4 z = make_uint4(0, 0, 0, 0);
        uint4* mz = (uint4*)sTile;     // tile, Adj, sTT contiguous: 54720 B
        for (int i = tid; i < 54720 / 16; i += BLK) mz[i] = z;
        if (tid < 100) sB1[tid] = b1[tid];
        if (tid < 20)  sB2[tid] = b2[tid];
        if (tid < 20)  shg[tid] = 0.f;
    }
    __syncthreads();   // S0

    // ---- phase 1: pack F into tile [s][k]; build adjacency ----
    {
        const float4* Fg = (const float4*)(feat + (size_t)g * NPG * 100);
        for (int i = tid; i < 2500; i += BLK) {
            float4 v = Fg[i];
            int s = i / 25, w = (i % 25) * 2;
            sTile[s * TSW + w]     = pack_bf(v.x, v.y);
            sTile[s * TSW + w + 1] = pack_bf(v.z, v.w);
        }
        if (tid < 100) {
            const int4* es = (const int4*)(edge_src + (size_t)g * NPG * DEG + tid * DEG);
            const int base = g * NPG;
            __nv_bfloat16* arow = (__nv_bfloat16*)(sAdj + tid * TSW);
            #pragma unroll
            for (int q = 0; q < 4; q++) {
                int4 e = es[q];
                int s0 = e.x - base, s1 = e.y - base, s2 = e.z - base, s3 = e.w - base;
                arow[s0] = __float2bfloat16(__bfloat162float(arow[s0]) + 0.0625f);
                arow[s1] = __float2bfloat16(__bfloat162float(arow[s1]) + 0.0625f);
                arow[s2] = __float2bfloat16(__bfloat162float(arow[s2]) + 0.0625f);
                arow[s3] = __float2bfloat16(__bfloat162float(arow[s3]) + 0.0625f);
            }
        }
    }
    __syncthreads();   // S1

    const int m0  = warp * 16;
    const int r0  = m0 + qg, r1 = m0 + 8 + qg;       // <= 111
    const int cr0 = (r0 > 99) ? 99 : r0;
    const int cr1 = (r1 > 99) ? 99 : r1;

    uint32_t outp[13][2];   // staged GEMM outputs (packed bf16 pairs)

    // ---- GEMM A (warps 0-6): P^T = W1 @ F^T; warp 7: z2/z3 ----
    if (warp < 7) {
        uint32_t aw[7][4];   // W1 A-fragments from GLOBAL (rows 104-111 zero-padded)
        #pragma unroll
        for (int kt = 0; kt < 7; kt++) {
            const int i0 = r0 * WSW + kt * 8 + tig;
            const int i1 = r1 * WSW + kt * 8 + tig;
            aw[kt][0] = W1b_g[i0];     aw[kt][1] = W1b_g[i1];
            aw[kt][2] = W1b_g[i0 + 4]; aw[kt][3] = W1b_g[i1 + 4];
        }
        #pragma unroll 1
        for (int nt = 0; nt < 13; nt++) {
            float acc[4] = {0.f, 0.f, 0.f, 0.f};
            #pragma unroll
            for (int kt = 0; kt < 7; kt++) {
                const int idx = (nt * 8 + qg) * TSW + kt * 8 + tig;
                mma_bf16(acc, aw[kt], sTile[idx], sTile[idx + 4]);
            }
            outp[nt][0] = pack_bf(acc[0], acc[1]);
            outp[nt][1] = pack_bf(acc[2], acc[3]);
        }
    } else {
        // warp 7: z2 = Wo2 @ (Wv2 @ self_feat[g]);  z3 = Wo3 @ (Wv3 @ x3d[g])
        float* vs2 = (float*)(sm + B_V2S);
        {
            const float4* xr = (const float4*)(self_feat + (size_t)g * 200);
            const float4* wr = (const float4*)(Wv2 + lane * 200);
            float acc = 0.f;
            #pragma unroll 5
            for (int p = 0; p < 50; p++) {
                float4 av = wr[p], bv = xr[p];
                acc += av.x * bv.x + av.y * bv.y + av.z * bv.z + av.w * bv.w;
            }
            vs2[lane] = acc;
        }
        __syncwarp();
        if (lane < 20) {
            const float* wo = Wo2 + lane * 32;
            float z = 0.f;
            #pragma unroll
            for (int j = 0; j < 32; j++) z += wo[j] * vs2[j];
            ((float*)(sm + B_Z2))[lane] = z;
        }
        __syncwarp();
        float* vs3 = (float*)(sm + B_V3S);
        {
            const float4* xr = (const float4*)(x3d + (size_t)g * 100);
            const float4* wr = (const float4*)(Wv3 + lane * 100);
            float acc = 0.f;
            #pragma unroll 5
            for (int p = 0; p < 25; p++) {
                float4 av = wr[p], bv = xr[p];
                acc += av.x * bv.x + av.y * bv.y + av.z * bv.z + av.w * bv.w;
            }
            vs3[lane] = acc;
        }
        __syncwarp();
        if (lane < 20) {
            const float* wo = Wo3 + lane * 32;
            float z = 0.f;
            #pragma unroll
            for (int j = 0; j < 32; j++) z += wo[j] * vs3[j];
            ((float*)(sm + B_Z3))[lane] = z;
        }
    }
    __syncthreads();   // S2: all F reads done

    // write P^T over tile (coalesced packed stores; rows 100-103 get zeros via W1 pad)
    if (warp < 7) {
        #pragma unroll
        for (int nt = 0; nt < 13; nt++) {
            const int w = nt * 4 + tig;        // = col/2, col = nt*8+2tig <= 102
            if (r0 < 104) sTile[r0 * TSW + w] = outp[nt][0];
            if (r1 < 104) sTile[r1 * TSW + w] = outp[nt][1];
        }
    }
    __syncthreads();   // S3: P^T ready

    // ---- GEMM B (warps 0-6): h1 = relu(Adj @ P + b1), staged in regs ----
    if (warp < 7) {
        uint32_t aa[7][4];
        #pragma unroll
        for (int kt = 0; kt < 7; kt++) {
            const int i0 = cr0 * TSW + kt * 8 + tig;
            const int i1 = cr1 * TSW + kt * 8 + tig;
            aa[kt][0] = sAdj[i0];     aa[kt][1] = sAdj[i1];
            aa[kt][2] = sAdj[i0 + 4]; aa[kt][3] = sAdj[i1 + 4];
        }
        #pragma unroll 1
        for (int nt = 0; nt < 13; nt++) {
            float acc[4] = {0.f, 0.f, 0.f, 0.f};
            #pragma unroll
            for (int kt = 0; kt < 7; kt++) {
                const int idx = (nt * 8 + qg) * TSW + kt * 8 + tig;
                mma_bf16(acc, aa[kt], sTile[idx], sTile[idx + 4]);
            }
            const int col = nt * 8 + 2 * tig;
            if (col < 100) {
                const float bx = sB1[col], by = sB1[col + 1];
                outp[nt][0] = pack_bf(fmaxf(acc[0] + bx, 0.f), fmaxf(acc[1] + by, 0.f));
                outp[nt][1] = pack_bf(fmaxf(acc[2] + bx, 0.f), fmaxf(acc[3] + by, 0.f));
            }
        }
    }
    __syncthreads();   // S4: all P^T reads done

    // write h1 over tile (rows<100, words<50; pads stay zero)
    if (warp < 7) {
        #pragma unroll
        for (int nt = 0; nt < 13; nt++) {
            const int col = nt * 8 + 2 * tig;
            if (col < 100) {
                const int w = nt * 4 + tig;
                if (r0 < 100) sTile[r0 * TSW + w] = outp[nt][0];
                if (r1 < 100) sTile[r1 * TSW + w] = outp[nt][1];
            }
        }
    }
    __syncthreads();   // S5: h1 ready

    // ---- GEMM C (warps 0-1): sT^T = W2 @ h1^T -> sSTT ----
    if (warp < 2) {
        uint32_t aw2[7][4];
        #pragma unroll
        for (int kt = 0; kt < 7; kt++) {
            const int i0 = r0 * WSW + kt * 8 + tig;   // r0 <= 31 (W2b 32 rows)
            const int i1 = r1 * WSW + kt * 8 + tig;
            aw2[kt][0] = W2b_g[i0];     aw2[kt][1] = W2b_g[i1];
            aw2[kt][2] = W2b_g[i0 + 4]; aw2[kt][3] = W2b_g[i1 + 4];
        }
        #pragma unroll 1
        for (int nt = 0; nt < 13; nt++) {
            float acc[4] = {0.f, 0.f, 0.f, 0.f};
            #pragma unroll
            for (int kt = 0; kt < 7; kt++) {
                const int idx = (nt * 8 + qg) * TSW + kt * 8 + tig;
                mma_bf16(acc, aw2[kt], sTile[idx], sTile[idx + 4]);
            }
            const int w = nt * 4 + tig;
            if (r0 < 20) sSTT[r0 * TSW + w] = pack_bf(acc[0], acc[1]);
            if (r1 < 20) sSTT[r1 * TSW + w] = pack_bf(acc[2], acc[3]);
        }
    }
    __syncthreads();   // S6: sT^T ready

    // ---- GEMM D (warps 0-6): h2 = relu(Adj @ sT + b2); hg accum ----
    if (warp < 7) {
        uint32_t aa[7][4];
        #pragma unroll
        for (int kt = 0; kt < 7; kt++) {
            const int i0 = cr0 * TSW + kt * 8 + tig;
            const int i1 = cr1 * TSW + kt * 8 + tig;
            aa[kt][0] = sAdj[i0];     aa[kt][1] = sAdj[i1];
            aa[kt][2] = sAdj[i0 + 4]; aa[kt][3] = sAdj[i1 + 4];
        }
        #pragma unroll
        for (int nt = 0; nt < 3; nt++) {
            float acc[4] = {0.f, 0.f, 0.f, 0.f};
            #pragma unroll
            for (int kt = 0; kt < 7; kt++) {
                const int idx = (nt * 8 + qg) * TSW + kt * 8 + tig;
                mma_bf16(acc, aa[kt], sSTT[idx], sSTT[idx + 4]);
            }
            const int col = nt * 8 + 2 * tig;
            if (col < 20) {
                const float bx = sB2[col], by = sB2[col + 1];
                float add0 = (r0 < 100 ? fmaxf(acc[0] + bx, 0.f) : 0.f)
                           + (r1 < 100 ? fmaxf(acc[2] + bx, 0.f) : 0.f);
                float add1 = (r0 < 100 ? fmaxf(acc[1] + by, 0.f) : 0.f)
                           + (r1 < 100 ? fmaxf(acc[3] + by, 0.f) : 0.f);
                atomicAdd(shg + col, add0);
                atomicAdd(shg + col + 1, add1);
            }
        }
    }
    __syncthreads();   // S7

    // ---- tail (warp 0): hg + z2 -> LN -> + z3 -> LN -> MLP ----
    if (warp == 0) {
        const float* z2 = (const float*)(sm + B_Z2);
        const float* z3 = (const float*)(sm + B_Z3);
        float* sVec = (float*)(sm + B_V2S);

        float y = 0.f;
        if (lane < 20) y = shg[lane] * (1.f / NPG) + z2[lane];
        float s = y;
        #pragma unroll
        for (int o = 16; o; o >>= 1) s += __shfl_xor_sync(0xffffffffu, s, o);
        float mu = s * (1.f / 20.f);
        float dd = (lane < 20) ? (y - mu) : 0.f;
        float vv = dd * dd;
        #pragma unroll
        for (int o = 16; o; o >>= 1) vv += __shfl_xor_sync(0xffffffffu, vv, o);
        float hg1 = 0.f;
        if (lane < 20)
            hg1 = dd * rsqrtf(vv * (1.f / 20.f) + 1e-5f) * g2[lane] + be2[lane];

        float y2 = (lane < 20) ? (hg1 + z3[lane]) : 0.f;
        float s2 = y2;
        #pragma unroll
        for (int o = 16; o; o >>= 1) s2 += __shfl_xor_sync(0xffffffffu, s2, o);
        float mu2 = s2 * (1.f / 20.f);
        float d2 = (lane < 20) ? (y2 - mu2) : 0.f;
        float v2s = d2 * d2;
        #pragma unroll
        for (int o = 16; o; o >>= 1) v2s += __shfl_xor_sync(0xffffffffu, v2s, o);
        float hg2 = 0.f;
        if (lane < 20)
            hg2 = d2 * rsqrtf(v2s * (1.f / 20.f) + 1e-5f) * g3[lane] + be3[lane];

        __syncwarp();
        if (lane < 20) sVec[lane] = hg2;
        __syncwarp();

        float f = 0.f;
        if (lane < 10) {
            const float* wf = Wf1 + lane * 20;
            float a = bf1[lane];
            #pragma unroll
            for (int k = 0; k < 20; k++) a += wf[k] * sVec[k];
            f = fmaxf(a, 0.f) * Wf2[lane];
        }
        #pragma unroll
        for (int o = 16; o; o >>= 1) f += __shfl_xor_sync(0xffffffffu, f, o);
        if (lane == 0) out[g] = f + bf2[0];
    }
}

// ============================ launch ============================
extern "C" void kernel_launch(void* const* d_in, const int* in_sizes, int n_in,
                              void* d_out, int out_size) {
    const float* feat      = (const float*)d_in[0];
    const int*   edge_src  = (const int*)  d_in[1];
    // d_in[2] = edge_dst: repeat(arange(N), DEG) by construction — implicit
    const float* self_feat = (const float*)d_in[3];
    const float* x3d       = (const float*)d_in[4];
    const float* W1  = (const float*)d_in[5];
    const float* b1  = (const float*)d_in[6];
    const float* W2  = (const float*)d_in[7];
    const float* b2  = (const float*)d_in[8];
    const float* Wv2 = (const float*)d_in[11];
    const float* Wo2 = (const float*)d_in[12];
    const float* g2  = (const float*)d_in[13];
    const float* be2 = (const float*)d_in[14];
    const float* Wv3 = (const float*)d_in[17];
    const float* Wo3 = (const float*)d_in[18];
    const float* g3  = (const float*)d_in[19];
    const float* be3 = (const float*)d_in[20];
    const float* Wf1 = (const float*)d_in[21];
    const float* bf1 = (const float*)d_in[22];
    const float* Wf2 = (const float*)d_in[23];
    const float* bf2 = (const float*)d_in[24];

    prep_kernel<<<(112 * WSW + 32 * WSW + 255) / 256, 256>>>(W1, W2);

    cudaFuncSetAttribute(gnn_fused_kernel,
                         cudaFuncAttributeMaxDynamicSharedMemorySize,
                         K_BYTES);
    gnn_fused_kernel<<<NGRAPH, BLK, K_BYTES>>>(
        feat, edge_src, self_feat, x3d,
        b1, b2,
        Wv2, Wo2, g2, be2,
        Wv3, Wo3, g3, be3,
        Wf1, bf1, Wf2, bf2,
        (float*)d_out);
}